// round 1
// baseline (speedup 1.0000x reference)
#include <cuda_runtime.h>
#include <math.h>

#define HIDDEN 1024
#define HEADS  16
#define HD     64
#define BATCH  4
#define SEQ    2048

// Scratch (device globals — no allocation allowed in kernel_launch)
__device__ float g_q[BATCH * HEADS * SEQ * HD];      // 32 MB
__device__ float g_k[BATCH * HEADS * SEQ * HD];      // 32 MB
__device__ float g_v[BATCH * HEADS * SEQ * HD];      // 32 MB
__device__ float g_attn[BATCH * SEQ * HIDDEN];       // 32 MB

// ---------------------------------------------------------------------------
// Tiled fp32 GEMM: C[M,N] = A[M,K] @ B[K,N] + bias[N]
// BM=128, BN=64, BK=16, 256 threads, 8x4 register tile per thread.
// mode 0: write C[m*N+n] (float4)
// mode 1: scatter into g_q/g_k/g_v as [B,H,S,HD] (QKV epilogue, transpose fused)
// Assumes M%128==0, N%64==0, K%16==0 (true for all our shapes).
// ---------------------------------------------------------------------------
__global__ __launch_bounds__(256) void gemm_kernel(
    const float* __restrict__ A, const float* __restrict__ B,
    const float* __restrict__ bias, float* __restrict__ C,
    int M, int N, int K, int mode)
{
    __shared__ float As[16][128 + 4];   // stored transposed: As[k][m]
    __shared__ float Bs[16][64];

    const int tid = threadIdx.x;
    const int tx = tid & 15;            // 0..15 -> 4 output cols
    const int ty = tid >> 4;            // 0..15 -> 8 output rows
    const int bm = blockIdx.y * 128;
    const int bn = blockIdx.x * 64;

    float acc[8][4];
    #pragma unroll
    for (int i = 0; i < 8; i++)
        #pragma unroll
        for (int j = 0; j < 4; j++) acc[i][j] = 0.f;

    for (int k0 = 0; k0 < K; k0 += 16) {
        __syncthreads();
        // Load A tile (128x16), store transposed
        #pragma unroll
        for (int u = 0; u < 2; u++) {
            int f4 = tid + u * 256;           // 0..511
            int r  = f4 >> 2;                 // 0..127
            int c4 = f4 & 3;                  // 0..3
            float4 v = *(const float4*)(A + (size_t)(bm + r) * K + k0 + c4 * 4);
            As[c4 * 4 + 0][r] = v.x;
            As[c4 * 4 + 1][r] = v.y;
            As[c4 * 4 + 2][r] = v.z;
            As[c4 * 4 + 3][r] = v.w;
        }
        // Load B tile (16x64)
        {
            int kr = tid >> 4;                // 0..15
            int c4 = tid & 15;                // 0..15
            *(float4*)&Bs[kr][c4 * 4] =
                *(const float4*)(B + (size_t)(k0 + kr) * N + bn + c4 * 4);
        }
        __syncthreads();

        #pragma unroll
        for (int k = 0; k < 16; k++) {
            float4 a0 = *(float4*)&As[k][ty * 8];
            float4 a1 = *(float4*)&As[k][ty * 8 + 4];
            float4 b0 = *(float4*)&Bs[k][tx * 4];
            float a[8] = {a0.x, a0.y, a0.z, a0.w, a1.x, a1.y, a1.z, a1.w};
            float bb[4] = {b0.x, b0.y, b0.z, b0.w};
            #pragma unroll
            for (int i = 0; i < 8; i++)
                #pragma unroll
                for (int j = 0; j < 4; j++)
                    acc[i][j] += a[i] * bb[j];
        }
    }

    // Epilogue
    const int n0 = bn + tx * 4;
    float4 bv = *(const float4*)(bias + n0);
    if (mode == 0) {
        #pragma unroll
        for (int i = 0; i < 8; i++) {
            int m = bm + ty * 8 + i;
            float4 r = {acc[i][0] + bv.x, acc[i][1] + bv.y,
                        acc[i][2] + bv.z, acc[i][3] + bv.w};
            *(float4*)(C + (size_t)m * N + n0) = r;
        }
    } else {
        // n0 decomposition constant per thread (bn%64==0, tx*4+3 < 64)
        int sel = n0 >> 10;                 // 0=q,1=k,2=v
        int rem = n0 & 1023;
        int h   = rem >> 6;
        int hd0 = rem & 63;                 // multiple of 4
        float* dst = (sel == 0) ? g_q : ((sel == 1) ? g_k : g_v);
        #pragma unroll
        for (int i = 0; i < 8; i++) {
            int m = bm + ty * 8 + i;
            int b = m >> 11;
            int s = m & 2047;
            float4 r = {acc[i][0] + bv.x, acc[i][1] + bv.y,
                        acc[i][2] + bv.z, acc[i][3] + bv.w};
            *(float4*)(dst + ((((size_t)b * HEADS + h) * SEQ) + s) * HD + hd0) = r;
        }
    }
}

// ---------------------------------------------------------------------------
// Flash attention (fp32). Grid: (SEQ/64, BATCH*HEADS). Block: 256 threads.
// Each block: 64 query rows, iterates 32-key tiles with online softmax.
// Thread (tx 0..15, ty 0..15): owns 4 query rows (ty*4+i), score cols
// {tx, 16+tx}, output head-dims tx*4..tx*4+3. Q pre-scaled by 1/sqrt(64).
// Writes output in [B,S,H*HD] layout for the output GEMM.
// ---------------------------------------------------------------------------
__global__ __launch_bounds__(256) void attn_kernel(
    const float* __restrict__ Q, const float* __restrict__ K,
    const float* __restrict__ V, float* __restrict__ O)
{
    __shared__ float Qs[64][68];
    __shared__ float Ks[32][68];
    __shared__ float Vs[32][68];
    __shared__ float Ps[64][33];

    const int tid = threadIdx.x;
    const int tx = tid & 15;
    const int ty = tid >> 4;
    const int bh = blockIdx.y;
    const int q0 = blockIdx.x * 64;

    const float* Qb = Q + ((size_t)bh * SEQ + q0) * HD;
    const float* Kb = K + (size_t)bh * SEQ * HD;
    const float* Vb = V + (size_t)bh * SEQ * HD;

    // Load Q tile, pre-scaled by 1/sqrt(HD) = 0.125
    #pragma unroll
    for (int u = 0; u < 4; u++) {
        int f4 = tid + u * 256;             // 0..1023
        int r  = f4 >> 4;                   // 0..63
        int c4 = f4 & 15;                   // 0..15
        float4 v = *(const float4*)(Qb + (size_t)r * HD + c4 * 4);
        Qs[r][c4 * 4 + 0] = v.x * 0.125f;
        Qs[r][c4 * 4 + 1] = v.y * 0.125f;
        Qs[r][c4 * 4 + 2] = v.z * 0.125f;
        Qs[r][c4 * 4 + 3] = v.w * 0.125f;
    }

    float m_i[4], l_i[4], o[4][4];
    #pragma unroll
    for (int i = 0; i < 4; i++) {
        m_i[i] = -INFINITY;
        l_i[i] = 0.f;
        #pragma unroll
        for (int j = 0; j < 4; j++) o[i][j] = 0.f;
    }

    for (int kt = 0; kt < SEQ / 32; kt++) {
        __syncthreads();
        #pragma unroll
        for (int u = 0; u < 2; u++) {
            int f4 = tid + u * 256;         // 0..511
            int r  = f4 >> 4;               // 0..31
            int c4 = f4 & 15;
            size_t goff = (size_t)(kt * 32 + r) * HD + c4 * 4;
            float4 kv = *(const float4*)(Kb + goff);
            Ks[r][c4 * 4 + 0] = kv.x; Ks[r][c4 * 4 + 1] = kv.y;
            Ks[r][c4 * 4 + 2] = kv.z; Ks[r][c4 * 4 + 3] = kv.w;
            float4 vv = *(const float4*)(Vb + goff);
            Vs[r][c4 * 4 + 0] = vv.x; Vs[r][c4 * 4 + 1] = vv.y;
            Vs[r][c4 * 4 + 2] = vv.z; Vs[r][c4 * 4 + 3] = vv.w;
        }
        __syncthreads();

        // Scores: s[i][j] = Qs[row] . Ks[col],  col = j*16 + tx
        float s[4][2];
        #pragma unroll
        for (int i = 0; i < 4; i++) { s[i][0] = 0.f; s[i][1] = 0.f; }
        #pragma unroll
        for (int d4 = 0; d4 < 16; d4++) {
            float4 b0 = *(float4*)&Ks[tx][d4 * 4];
            float4 b1 = *(float4*)&Ks[16 + tx][d4 * 4];
            #pragma unroll
            for (int i = 0; i < 4; i++) {
                float4 a = *(float4*)&Qs[ty * 4 + i][d4 * 4];
                s[i][0] += a.x * b0.x + a.y * b0.y + a.z * b0.z + a.w * b0.w;
                s[i][1] += a.x * b1.x + a.y * b1.y + a.z * b1.z + a.w * b1.w;
            }
        }

        // Online softmax (row reductions across tx via width-16 shuffles)
        #pragma unroll
        for (int i = 0; i < 4; i++) {
            float mx = fmaxf(s[i][0], s[i][1]);
            #pragma unroll
            for (int w = 1; w < 16; w <<= 1)
                mx = fmaxf(mx, __shfl_xor_sync(0xffffffffu, mx, w, 16));
            float mn = fmaxf(m_i[i], mx);
            float alpha = __expf(m_i[i] - mn);
            float p0 = __expf(s[i][0] - mn);
            float p1 = __expf(s[i][1] - mn);
            float rs = p0 + p1;
            #pragma unroll
            for (int w = 1; w < 16; w <<= 1)
                rs += __shfl_xor_sync(0xffffffffu, rs, w, 16);
            l_i[i] = l_i[i] * alpha + rs;
            m_i[i] = mn;
            #pragma unroll
            for (int j = 0; j < 4; j++) o[i][j] *= alpha;
            Ps[ty * 4 + i][tx]      = p0;
            Ps[ty * 4 + i][16 + tx] = p1;
        }
        __syncwarp();

        // O += P @ V
        #pragma unroll
        for (int c = 0; c < 32; c++) {
            float4 v = *(float4*)&Vs[c][tx * 4];
            #pragma unroll
            for (int i = 0; i < 4; i++) {
                float p = Ps[ty * 4 + i][c];
                o[i][0] += p * v.x;
                o[i][1] += p * v.y;
                o[i][2] += p * v.z;
                o[i][3] += p * v.w;
            }
        }
    }

    // Write output in [B, S, H*HD] layout
    const int b = bh >> 4;
    const int h = bh & 15;
    #pragma unroll
    for (int i = 0; i < 4; i++) {
        int srow = q0 + ty * 4 + i;
        float inv = 1.0f / l_i[i];
        float4 r = {o[i][0] * inv, o[i][1] * inv, o[i][2] * inv, o[i][3] * inv};
        *(float4*)(O + ((size_t)b * SEQ + srow) * HIDDEN + h * HD + tx * 4) = r;
    }
}

// ---------------------------------------------------------------------------
extern "C" void kernel_launch(void* const* d_in, const int* in_sizes, int n_in,
                              void* d_out, int out_size)
{
    const float* x     = (const float*)d_in[0];   // [4,2048,1024]
    const float* W_qkv = (const float*)d_in[1];   // [1024,3072]
    const float* b_qkv = (const float*)d_in[2];   // [3072]
    const float* W_out = (const float*)d_in[3];   // [1024,1024]
    const float* b_out = (const float*)d_in[4];   // [1024]
    float* out = (float*)d_out;                   // [4,2048,1024]

    const int M = BATCH * SEQ;                    // 8192

    // 1) QKV projection, scatter to head-major Q/K/V
    {
        dim3 grid(3 * HIDDEN / 64, M / 128);
        gemm_kernel<<<grid, 256>>>(x, W_qkv, b_qkv, nullptr,
                                   M, 3 * HIDDEN, HIDDEN, /*mode=*/1);
    }

    // 2) Attention
    {
        // need device-global pointers; kernels reference them via args
        // (addresses of __device__ arrays are valid in device code; pass via
        //  a tiny launch that takes them directly)
        dim3 grid(SEQ / 64, BATCH * HEADS);
        // g_q/g_k/g_v/g_attn are module-scope device arrays; their addresses
        // can be taken in host code only via cudaGetSymbolAddress — instead the
        // kernel parameters below are bound by a helper kernel-side alias:
        // simplest: pass nullptrs and have attn_kernel use globals? We pass
        // via cudaGetSymbolAddress (host API, not a stream op, capture-safe).
        static float *pq = nullptr, *pk = nullptr, *pv = nullptr, *pa = nullptr;
        if (!pq) {
            cudaGetSymbolAddress((void**)&pq, g_q);
            cudaGetSymbolAddress((void**)&pk, g_k);
            cudaGetSymbolAddress((void**)&pv, g_v);
            cudaGetSymbolAddress((void**)&pa, g_attn);
        }
        attn_kernel<<<grid, 256>>>(pq, pk, pv, pa);

        // 3) Output projection
        dim3 grid2(HIDDEN / 64, M / 128);
        gemm_kernel<<<grid2, 256>>>(pa, W_out, b_out, out,
                                    M, HIDDEN, HIDDEN, /*mode=*/0);
    }
}

// round 3
// speedup vs baseline: 1.1867x; 1.1867x over previous
#include <cuda_runtime.h>
#include <cuda_bf16.h>
#include <math.h>
#include <stdint.h>

#define HIDDEN 1024
#define HEADS  16
#define HD     64
#define BATCH  4
#define SEQ    2048
#define MTOT   (BATCH * SEQ)   // 8192

// ---------------- scratch (device globals; no allocs allowed) --------------
__device__ float g_q[BATCH * HEADS * SEQ * HD];
__device__ float g_k[BATCH * HEADS * SEQ * HD];
__device__ float g_v[BATCH * HEADS * SEQ * HD];

__device__ __nv_bfloat16 g_a_hi[MTOT * HIDDEN];        // activation split (reused)
__device__ __nv_bfloat16 g_a_lo[MTOT * HIDDEN];
__device__ __nv_bfloat16 g_wq_hi[3 * HIDDEN * HIDDEN]; // W_qkv^T  [3072,1024]
__device__ __nv_bfloat16 g_wq_lo[3 * HIDDEN * HIDDEN];
__device__ __nv_bfloat16 g_wo_hi[HIDDEN * HIDDEN];     // W_out^T  [1024,1024]
__device__ __nv_bfloat16 g_wo_lo[HIDDEN * HIDDEN];

// ---------------------------------------------------------------------------
// split: x -> bf16 hi + bf16 lo  (one float4 per thread)
// ---------------------------------------------------------------------------
__global__ __launch_bounds__(256) void split_kernel(
    const float* __restrict__ src, __nv_bfloat16* __restrict__ hi,
    __nv_bfloat16* __restrict__ lo, int n4)
{
    int i = blockIdx.x * blockDim.x + threadIdx.x;
    if (i >= n4) return;
    float4 v = ((const float4*)src)[i];
    float xs[4] = {v.x, v.y, v.z, v.w};
    __nv_bfloat16 h[4], l[4];
    #pragma unroll
    for (int j = 0; j < 4; j++) {
        h[j] = __float2bfloat16_rn(xs[j]);
        l[j] = __float2bfloat16_rn(xs[j] - __bfloat162float(h[j]));
    }
    ((__nv_bfloat162*)hi)[2 * i]     = __nv_bfloat162(h[0], h[1]);
    ((__nv_bfloat162*)hi)[2 * i + 1] = __nv_bfloat162(h[2], h[3]);
    ((__nv_bfloat162*)lo)[2 * i]     = __nv_bfloat162(l[0], l[1]);
    ((__nv_bfloat162*)lo)[2 * i + 1] = __nv_bfloat162(l[2], l[3]);
}

// ---------------------------------------------------------------------------
// transpose + split: W[K,N] fp32 -> Wt_hi/Wt_lo [N,K] bf16
// ---------------------------------------------------------------------------
__global__ void tsplit_kernel(const float* __restrict__ W,
                              __nv_bfloat16* __restrict__ hi,
                              __nv_bfloat16* __restrict__ lo, int K, int N)
{
    __shared__ float t[32][33];
    int n0 = blockIdx.x * 32, k0 = blockIdx.y * 32;
    for (int r = threadIdx.y; r < 32; r += 8)
        t[r][threadIdx.x] = W[(size_t)(k0 + r) * N + n0 + threadIdx.x];
    __syncthreads();
    for (int r = threadIdx.y; r < 32; r += 8) {
        float x = t[threadIdx.x][r];   // = W[k0+tx][n0+r]
        __nv_bfloat16 h = __float2bfloat16_rn(x);
        __nv_bfloat16 l = __float2bfloat16_rn(x - __bfloat162float(h));
        size_t o = (size_t)(n0 + r) * K + k0 + threadIdx.x;
        hi[o] = h;
        lo[o] = l;
    }
}

// ---------------------------------------------------------------------------
// HMMA bf16 GEMM (mma.sync m16n8k16): C[M,N] = (Ahi+Alo) @ (Bhi+Blo)^T + bias
// using 3 passes: Ahi*Bhi + Ahi*Blo + Alo*Bhi  (fp32 accumulate).
// A: [M,K] row-major bf16 (hi/lo).  B: [N,K] row-major bf16 (hi/lo).
// Tile BM=128, BN=128, BK=32. 8 warps (2 x 4), warp tile 64x32.
// mode 0: write C + bias.  mode 1: QKV scatter to q/k/v [B,H,S,64].
// ---------------------------------------------------------------------------
__device__ __forceinline__ void mma16816(float* c, const uint32_t* a, const uint32_t* b)
{
    asm volatile(
        "mma.sync.aligned.m16n8k16.row.col.f32.bf16.bf16.f32 "
        "{%0,%1,%2,%3}, {%4,%5,%6,%7}, {%8,%9}, {%0,%1,%2,%3};"
        : "+f"(c[0]), "+f"(c[1]), "+f"(c[2]), "+f"(c[3])
        : "r"(a[0]), "r"(a[1]), "r"(a[2]), "r"(a[3]), "r"(b[0]), "r"(b[1]));
}

#define SPAD 40   // smem row stride in bf16 (80B): conflict-free fragment loads

__global__ __launch_bounds__(256) void hmma_gemm(
    const __nv_bfloat16* __restrict__ Ahi, const __nv_bfloat16* __restrict__ Alo,
    const __nv_bfloat16* __restrict__ Bhi, const __nv_bfloat16* __restrict__ Blo,
    const float* __restrict__ bias, float* __restrict__ C,
    float* __restrict__ q, float* __restrict__ k_, float* __restrict__ v_,
    int M, int N, int K, int mode)
{
    __shared__ __nv_bfloat16 sAh[128][SPAD], sAl[128][SPAD];
    __shared__ __nv_bfloat16 sBh[128][SPAD], sBl[128][SPAD];

    const int tid  = threadIdx.x;
    const int wid  = tid >> 5;
    const int lane = tid & 31;
    const int grp  = lane >> 2;      // 0..7
    const int tig  = lane & 3;       // 0..3
    const int wm   = wid & 1;        // 2 warps over M
    const int wn   = wid >> 1;       // 4 warps over N
    const int bm   = blockIdx.y * 128;
    const int bn   = blockIdx.x * 128;

    float c[4][4][4];
    #pragma unroll
    for (int i = 0; i < 4; i++)
        #pragma unroll
        for (int j = 0; j < 4; j++)
            #pragma unroll
            for (int p = 0; p < 4; p++) c[i][j][p] = 0.f;

    for (int kt = 0; kt < K / 32; kt++) {
        const int k0 = kt * 32;
        __syncthreads();
        // load 128x32 bf16 tiles (4 of them): 512 uint4 granules each, 2/thread
        #pragma unroll
        for (int u = 0; u < 2; u++) {
            int gg = tid + u * 256;
            int r = gg >> 2, ch = gg & 3;
            size_t ga = (size_t)(bm + r) * K + k0 + ch * 8;
            size_t gb = (size_t)(bn + r) * K + k0 + ch * 8;
            *(uint4*)&sAh[r][ch * 8] = *(const uint4*)(Ahi + ga);
            *(uint4*)&sAl[r][ch * 8] = *(const uint4*)(Alo + ga);
            *(uint4*)&sBh[r][ch * 8] = *(const uint4*)(Bhi + gb);
            *(uint4*)&sBl[r][ch * 8] = *(const uint4*)(Blo + gb);
        }
        __syncthreads();

        #pragma unroll
        for (int ks = 0; ks < 2; ks++) {
            const int kk = ks * 16 + tig * 2;
            uint32_t ah[4][4], bh[4][2];
            #pragma unroll
            for (int i = 0; i < 4; i++) {
                int ar = wm * 64 + i * 16 + grp;
                ah[i][0] = *(const uint32_t*)&sAh[ar][kk];
                ah[i][1] = *(const uint32_t*)&sAh[ar + 8][kk];
                ah[i][2] = *(const uint32_t*)&sAh[ar][kk + 8];
                ah[i][3] = *(const uint32_t*)&sAh[ar + 8][kk + 8];
            }
            #pragma unroll
            for (int j = 0; j < 4; j++) {
                int br = wn * 32 + j * 8 + grp;
                bh[j][0] = *(const uint32_t*)&sBh[br][kk];
                bh[j][1] = *(const uint32_t*)&sBh[br][kk + 8];
            }
            // pass 1: Ahi * Bhi
            #pragma unroll
            for (int i = 0; i < 4; i++)
                #pragma unroll
                for (int j = 0; j < 4; j++) mma16816(c[i][j], ah[i], bh[j]);
            // pass 2: Ahi * Blo
            uint32_t bl[4][2];
            #pragma unroll
            for (int j = 0; j < 4; j++) {
                int br = wn * 32 + j * 8 + grp;
                bl[j][0] = *(const uint32_t*)&sBl[br][kk];
                bl[j][1] = *(const uint32_t*)&sBl[br][kk + 8];
            }
            #pragma unroll
            for (int i = 0; i < 4; i++)
                #pragma unroll
                for (int j = 0; j < 4; j++) mma16816(c[i][j], ah[i], bl[j]);
            // pass 3: Alo * Bhi
            uint32_t al[4][4];
            #pragma unroll
            for (int i = 0; i < 4; i++) {
                int ar = wm * 64 + i * 16 + grp;
                al[i][0] = *(const uint32_t*)&sAl[ar][kk];
                al[i][1] = *(const uint32_t*)&sAl[ar + 8][kk];
                al[i][2] = *(const uint32_t*)&sAl[ar][kk + 8];
                al[i][3] = *(const uint32_t*)&sAl[ar + 8][kk + 8];
            }
            #pragma unroll
            for (int i = 0; i < 4; i++)
                #pragma unroll
                for (int j = 0; j < 4; j++) mma16816(c[i][j], al[i], bh[j]);
        }
    }

    // Epilogue: each thread owns rows {base, base+8} x col pairs per (i,j)
    #pragma unroll
    for (int i = 0; i < 4; i++) {
        #pragma unroll
        for (int j = 0; j < 4; j++) {
            int n0 = bn + wn * 32 + j * 8 + tig * 2;
            float2 bv = *(const float2*)(bias + n0);
            #pragma unroll
            for (int half = 0; half < 2; half++) {
                int m = bm + wm * 64 + i * 16 + grp + half * 8;
                float2 r = {c[i][j][half * 2 + 0] + bv.x,
                            c[i][j][half * 2 + 1] + bv.y};
                if (mode == 0) {
                    *(float2*)(C + (size_t)m * N + n0) = r;
                } else {
                    int sel = n0 >> 10, rem = n0 & 1023;
                    int h = rem >> 6, hd0 = rem & 63;
                    int b = m >> 11, s = m & 2047;
                    float* base = (sel == 0) ? q : ((sel == 1) ? k_ : v_);
                    *(float2*)(base + (((size_t)b * HEADS + h) * SEQ + s) * HD + hd0) = r;
                }
            }
        }
    }
}

// ---------------------------------------------------------------------------
// Flash attention (fp32), output written directly as bf16 hi/lo split
// in [B, S, H*HD] layout (feeds the HMMA output projection).
// ---------------------------------------------------------------------------
__global__ __launch_bounds__(256) void attn_kernel(
    const float* __restrict__ Q, const float* __restrict__ K,
    const float* __restrict__ V,
    __nv_bfloat16* __restrict__ Ohi, __nv_bfloat16* __restrict__ Olo)
{
    __shared__ float Qs[64][68];
    __shared__ float Ks[32][68];
    __shared__ float Vs[32][68];
    __shared__ float Ps[64][33];

    const int tid = threadIdx.x;
    const int tx = tid & 15;
    const int ty = tid >> 4;
    const int bh = blockIdx.y;
    const int q0 = blockIdx.x * 64;

    const float* Qb = Q + ((size_t)bh * SEQ + q0) * HD;
    const float* Kb = K + (size_t)bh * SEQ * HD;
    const float* Vb = V + (size_t)bh * SEQ * HD;

    #pragma unroll
    for (int u = 0; u < 4; u++) {
        int f4 = tid + u * 256;
        int r = f4 >> 4, c4 = f4 & 15;
        float4 v = *(const float4*)(Qb + (size_t)r * HD + c4 * 4);
        Qs[r][c4 * 4 + 0] = v.x * 0.125f;
        Qs[r][c4 * 4 + 1] = v.y * 0.125f;
        Qs[r][c4 * 4 + 2] = v.z * 0.125f;
        Qs[r][c4 * 4 + 3] = v.w * 0.125f;
    }

    float m_i[4], l_i[4], o[4][4];
    #pragma unroll
    for (int i = 0; i < 4; i++) {
        m_i[i] = -INFINITY;
        l_i[i] = 0.f;
        #pragma unroll
        for (int j = 0; j < 4; j++) o[i][j] = 0.f;
    }

    for (int kt = 0; kt < SEQ / 32; kt++) {
        __syncthreads();
        #pragma unroll
        for (int u = 0; u < 2; u++) {
            int f4 = tid + u * 256;
            int r = f4 >> 4, c4 = f4 & 15;
            size_t goff = (size_t)(kt * 32 + r) * HD + c4 * 4;
            float4 kv = *(const float4*)(Kb + goff);
            Ks[r][c4 * 4 + 0] = kv.x; Ks[r][c4 * 4 + 1] = kv.y;
            Ks[r][c4 * 4 + 2] = kv.z; Ks[r][c4 * 4 + 3] = kv.w;
            float4 vv = *(const float4*)(Vb + goff);
            Vs[r][c4 * 4 + 0] = vv.x; Vs[r][c4 * 4 + 1] = vv.y;
            Vs[r][c4 * 4 + 2] = vv.z; Vs[r][c4 * 4 + 3] = vv.w;
        }
        __syncthreads();

        float s[4][2];
        #pragma unroll
        for (int i = 0; i < 4; i++) { s[i][0] = 0.f; s[i][1] = 0.f; }
        #pragma unroll
        for (int d4 = 0; d4 < 16; d4++) {
            float4 b0 = *(float4*)&Ks[tx][d4 * 4];
            float4 b1 = *(float4*)&Ks[16 + tx][d4 * 4];
            #pragma unroll
            for (int i = 0; i < 4; i++) {
                float4 a = *(float4*)&Qs[ty * 4 + i][d4 * 4];
                s[i][0] += a.x * b0.x + a.y * b0.y + a.z * b0.z + a.w * b0.w;
                s[i][1] += a.x * b1.x + a.y * b1.y + a.z * b1.z + a.w * b1.w;
            }
        }

        #pragma unroll
        for (int i = 0; i < 4; i++) {
            float mx = fmaxf(s[i][0], s[i][1]);
            #pragma unroll
            for (int w = 1; w < 16; w <<= 1)
                mx = fmaxf(mx, __shfl_xor_sync(0xffffffffu, mx, w, 16));
            float mn = fmaxf(m_i[i], mx);
            float alpha = __expf(m_i[i] - mn);
            float p0 = __expf(s[i][0] - mn);
            float p1 = __expf(s[i][1] - mn);
            float rs = p0 + p1;
            #pragma unroll
            for (int w = 1; w < 16; w <<= 1)
                rs += __shfl_xor_sync(0xffffffffu, rs, w, 16);
            l_i[i] = l_i[i] * alpha + rs;
            m_i[i] = mn;
            #pragma unroll
            for (int j = 0; j < 4; j++) o[i][j] *= alpha;
            Ps[ty * 4 + i][tx]      = p0;
            Ps[ty * 4 + i][16 + tx] = p1;
        }
        __syncwarp();

        #pragma unroll
        for (int ccol = 0; ccol < 32; ccol++) {
            float4 v = *(float4*)&Vs[ccol][tx * 4];
            #pragma unroll
            for (int i = 0; i < 4; i++) {
                float p = Ps[ty * 4 + i][ccol];
                o[i][0] += p * v.x;
                o[i][1] += p * v.y;
                o[i][2] += p * v.z;
                o[i][3] += p * v.w;
            }
        }
    }

    const int b = bh >> 4;
    const int h = bh & 15;
    #pragma unroll
    for (int i = 0; i < 4; i++) {
        int srow = q0 + ty * 4 + i;
        float inv = 1.0f / l_i[i];
        float r[4] = {o[i][0] * inv, o[i][1] * inv, o[i][2] * inv, o[i][3] * inv};
        size_t off = ((size_t)b * SEQ + srow) * HIDDEN + h * HD + tx * 4;
        __nv_bfloat16 hh[4], ll[4];
        #pragma unroll
        for (int j = 0; j < 4; j++) {
            hh[j] = __float2bfloat16_rn(r[j]);
            ll[j] = __float2bfloat16_rn(r[j] - __bfloat162float(hh[j]));
        }
        *(__nv_bfloat162*)(Ohi + off)     = __nv_bfloat162(hh[0], hh[1]);
        *(__nv_bfloat162*)(Ohi + off + 2) = __nv_bfloat162(hh[2], hh[3]);
        *(__nv_bfloat162*)(Olo + off)     = __nv_bfloat162(ll[0], ll[1]);
        *(__nv_bfloat162*)(Olo + off + 2) = __nv_bfloat162(ll[2], ll[3]);
    }
}

// ---------------------------------------------------------------------------
extern "C" void kernel_launch(void* const* d_in, const int* in_sizes, int n_in,
                              void* d_out, int out_size)
{
    const float* x     = (const float*)d_in[0];
    const float* W_qkv = (const float*)d_in[1];
    const float* b_qkv = (const float*)d_in[2];
    const float* W_out = (const float*)d_in[3];
    const float* b_out = (const float*)d_in[4];
    float* out = (float*)d_out;

    static float *pq = nullptr, *pk = nullptr, *pv = nullptr;
    static __nv_bfloat16 *pah, *pal, *pwqh, *pwql, *pwoh, *pwol;
    if (!pq) {
        cudaGetSymbolAddress((void**)&pq, g_q);
        cudaGetSymbolAddress((void**)&pk, g_k);
        cudaGetSymbolAddress((void**)&pv, g_v);
        cudaGetSymbolAddress((void**)&pah, g_a_hi);
        cudaGetSymbolAddress((void**)&pal, g_a_lo);
        cudaGetSymbolAddress((void**)&pwqh, g_wq_hi);
        cudaGetSymbolAddress((void**)&pwql, g_wq_lo);
        cudaGetSymbolAddress((void**)&pwoh, g_wo_hi);
        cudaGetSymbolAddress((void**)&pwol, g_wo_lo);
    }

    const int n4 = MTOT * HIDDEN / 4;

    // 1) split x and weights to bf16 hi/lo
    split_kernel<<<n4 / 256, 256>>>(x, pah, pal, n4);
    {
        dim3 g(3 * HIDDEN / 32, HIDDEN / 32);
        tsplit_kernel<<<g, dim3(32, 8)>>>(W_qkv, pwqh, pwql, HIDDEN, 3 * HIDDEN);
    }
    {
        dim3 g(HIDDEN / 32, HIDDEN / 32);
        tsplit_kernel<<<g, dim3(32, 8)>>>(W_out, pwoh, pwol, HIDDEN, HIDDEN);
    }

    // 2) QKV projection (HMMA), scatter head-major fp32 Q/K/V
    {
        dim3 g(3 * HIDDEN / 128, MTOT / 128);   // (24, 64)
        hmma_gemm<<<g, 256>>>(pah, pal, pwqh, pwql, b_qkv, nullptr,
                              pq, pk, pv, MTOT, 3 * HIDDEN, HIDDEN, 1);
    }

    // 3) attention (fp32), emits bf16 hi/lo directly (reuses g_a_hi/g_a_lo)
    {
        dim3 g(SEQ / 64, BATCH * HEADS);
        attn_kernel<<<g, 256>>>(pq, pk, pv, pah, pal);
    }

    // 4) output projection (HMMA) -> d_out
    {
        dim3 g(HIDDEN / 128, MTOT / 128);       // (8, 64)
        hmma_gemm<<<g, 256>>>(pah, pal, pwoh, pwol, b_out, out,
                              nullptr, nullptr, nullptr,
                              MTOT, HIDDEN, HIDDEN, 0);
    }
}

// round 4
// speedup vs baseline: 2.3092x; 1.9459x over previous
#include <cuda_runtime.h>
#include <cuda_bf16.h>
#include <math.h>
#include <stdint.h>

#define HIDDEN 1024
#define HEADS  16
#define HD     64
#define BATCH  4
#define SEQ    2048
#define MTOT   (BATCH * SEQ)   // 8192

// ---------------- scratch (device globals; no allocs allowed) --------------
__device__ __nv_bfloat16 g_a_hi[MTOT * HIDDEN];        // activation split (reused)
__device__ __nv_bfloat16 g_a_lo[MTOT * HIDDEN];
__device__ __nv_bfloat16 g_wq_hi[3 * HIDDEN * HIDDEN]; // W_qkv^T  [3072,1024]
__device__ __nv_bfloat16 g_wq_lo[3 * HIDDEN * HIDDEN];
__device__ __nv_bfloat16 g_wo_hi[HIDDEN * HIDDEN];     // W_out^T  [1024,1024]
__device__ __nv_bfloat16 g_wo_lo[HIDDEN * HIDDEN];
// attention operands, bf16 hi/lo
__device__ __nv_bfloat16 g_qh[BATCH * HEADS * SEQ * HD];  // [B,H,S,64], pre-scaled
__device__ __nv_bfloat16 g_ql[BATCH * HEADS * SEQ * HD];
__device__ __nv_bfloat16 g_kh[BATCH * HEADS * SEQ * HD];  // [B,H,S,64]
__device__ __nv_bfloat16 g_kl[BATCH * HEADS * SEQ * HD];
__device__ __nv_bfloat16 g_vth[BATCH * HEADS * HD * SEQ]; // [B,H,64,S]  (V^T)
__device__ __nv_bfloat16 g_vtl[BATCH * HEADS * HD * SEQ];

// ---------------------------------------------------------------------------
__global__ __launch_bounds__(256) void split_kernel(
    const float* __restrict__ src, __nv_bfloat16* __restrict__ hi,
    __nv_bfloat16* __restrict__ lo, int n4)
{
    int i = blockIdx.x * blockDim.x + threadIdx.x;
    if (i >= n4) return;
    float4 v = ((const float4*)src)[i];
    float xs[4] = {v.x, v.y, v.z, v.w};
    __nv_bfloat16 h[4], l[4];
    #pragma unroll
    for (int j = 0; j < 4; j++) {
        h[j] = __float2bfloat16_rn(xs[j]);
        l[j] = __float2bfloat16_rn(xs[j] - __bfloat162float(h[j]));
    }
    ((__nv_bfloat162*)hi)[2 * i]     = __nv_bfloat162(h[0], h[1]);
    ((__nv_bfloat162*)hi)[2 * i + 1] = __nv_bfloat162(h[2], h[3]);
    ((__nv_bfloat162*)lo)[2 * i]     = __nv_bfloat162(l[0], l[1]);
    ((__nv_bfloat162*)lo)[2 * i + 1] = __nv_bfloat162(l[2], l[3]);
}

__global__ void tsplit_kernel(const float* __restrict__ W,
                              __nv_bfloat16* __restrict__ hi,
                              __nv_bfloat16* __restrict__ lo, int K, int N)
{
    __shared__ float t[32][33];
    int n0 = blockIdx.x * 32, k0 = blockIdx.y * 32;
    for (int r = threadIdx.y; r < 32; r += 8)
        t[r][threadIdx.x] = W[(size_t)(k0 + r) * N + n0 + threadIdx.x];
    __syncthreads();
    for (int r = threadIdx.y; r < 32; r += 8) {
        float x = t[threadIdx.x][r];
        __nv_bfloat16 h = __float2bfloat16_rn(x);
        __nv_bfloat16 l = __float2bfloat16_rn(x - __bfloat162float(h));
        size_t o = (size_t)(n0 + r) * K + k0 + threadIdx.x;
        hi[o] = h;
        lo[o] = l;
    }
}

// ---------------------------------------------------------------------------
__device__ __forceinline__ void mma16816(float* c, const uint32_t* a, const uint32_t* b)
{
    asm volatile(
        "mma.sync.aligned.m16n8k16.row.col.f32.bf16.bf16.f32 "
        "{%0,%1,%2,%3}, {%4,%5,%6,%7}, {%8,%9}, {%0,%1,%2,%3};"
        : "+f"(c[0]), "+f"(c[1]), "+f"(c[2]), "+f"(c[3])
        : "r"(a[0]), "r"(a[1]), "r"(a[2]), "r"(a[3]), "r"(b[0]), "r"(b[1]));
}

__device__ __forceinline__ __nv_bfloat162 split_pack(float x, float y,
                                                     __nv_bfloat162* lo)
{
    __nv_bfloat16 hx = __float2bfloat16_rn(x);
    __nv_bfloat16 hy = __float2bfloat16_rn(y);
    *lo = __nv_bfloat162(__float2bfloat16_rn(x - __bfloat162float(hx)),
                         __float2bfloat16_rn(y - __bfloat162float(hy)));
    return __nv_bfloat162(hx, hy);
}

#define SPAD 40

// ---------------------------------------------------------------------------
// HMMA GEMM (3-pass hi/lo split). mode 0: C + bias. mode 1: QKV epilogue ->
// Q (scaled .125) / K bf16 hi/lo [B,H,S,64], V^T bf16 hi/lo [B,H,64,S].
// ---------------------------------------------------------------------------
__global__ __launch_bounds__(256) void hmma_gemm(
    const __nv_bfloat16* __restrict__ Ahi, const __nv_bfloat16* __restrict__ Alo,
    const __nv_bfloat16* __restrict__ Bhi, const __nv_bfloat16* __restrict__ Blo,
    const float* __restrict__ bias, float* __restrict__ C,
    __nv_bfloat16* __restrict__ qh, __nv_bfloat16* __restrict__ ql,
    __nv_bfloat16* __restrict__ kh, __nv_bfloat16* __restrict__ kl,
    __nv_bfloat16* __restrict__ vth, __nv_bfloat16* __restrict__ vtl,
    int M, int N, int K, int mode)
{
    __shared__ __nv_bfloat16 sAh[128][SPAD], sAl[128][SPAD];
    __shared__ __nv_bfloat16 sBh[128][SPAD], sBl[128][SPAD];

    const int tid  = threadIdx.x;
    const int wid  = tid >> 5;
    const int lane = tid & 31;
    const int grp  = lane >> 2;
    const int tig  = lane & 3;
    const int wm   = wid & 1;
    const int wn   = wid >> 1;
    const int bm   = blockIdx.y * 128;
    const int bn   = blockIdx.x * 128;

    float c[4][4][4];
    #pragma unroll
    for (int i = 0; i < 4; i++)
        #pragma unroll
        for (int j = 0; j < 4; j++)
            #pragma unroll
            for (int p = 0; p < 4; p++) c[i][j][p] = 0.f;

    for (int kt = 0; kt < K / 32; kt++) {
        const int k0 = kt * 32;
        __syncthreads();
        #pragma unroll
        for (int u = 0; u < 2; u++) {
            int gg = tid + u * 256;
            int r = gg >> 2, ch = gg & 3;
            size_t ga = (size_t)(bm + r) * K + k0 + ch * 8;
            size_t gb = (size_t)(bn + r) * K + k0 + ch * 8;
            *(uint4*)&sAh[r][ch * 8] = *(const uint4*)(Ahi + ga);
            *(uint4*)&sAl[r][ch * 8] = *(const uint4*)(Alo + ga);
            *(uint4*)&sBh[r][ch * 8] = *(const uint4*)(Bhi + gb);
            *(uint4*)&sBl[r][ch * 8] = *(const uint4*)(Blo + gb);
        }
        __syncthreads();

        #pragma unroll
        for (int ks = 0; ks < 2; ks++) {
            const int kk = ks * 16 + tig * 2;
            uint32_t ah[4][4], bh[4][2];
            #pragma unroll
            for (int i = 0; i < 4; i++) {
                int ar = wm * 64 + i * 16 + grp;
                ah[i][0] = *(const uint32_t*)&sAh[ar][kk];
                ah[i][1] = *(const uint32_t*)&sAh[ar + 8][kk];
                ah[i][2] = *(const uint32_t*)&sAh[ar][kk + 8];
                ah[i][3] = *(const uint32_t*)&sAh[ar + 8][kk + 8];
            }
            #pragma unroll
            for (int j = 0; j < 4; j++) {
                int br = wn * 32 + j * 8 + grp;
                bh[j][0] = *(const uint32_t*)&sBh[br][kk];
                bh[j][1] = *(const uint32_t*)&sBh[br][kk + 8];
            }
            #pragma unroll
            for (int i = 0; i < 4; i++)
                #pragma unroll
                for (int j = 0; j < 4; j++) mma16816(c[i][j], ah[i], bh[j]);
            uint32_t bl[4][2];
            #pragma unroll
            for (int j = 0; j < 4; j++) {
                int br = wn * 32 + j * 8 + grp;
                bl[j][0] = *(const uint32_t*)&sBl[br][kk];
                bl[j][1] = *(const uint32_t*)&sBl[br][kk + 8];
            }
            #pragma unroll
            for (int i = 0; i < 4; i++)
                #pragma unroll
                for (int j = 0; j < 4; j++) mma16816(c[i][j], ah[i], bl[j]);
            uint32_t al[4][4];
            #pragma unroll
            for (int i = 0; i < 4; i++) {
                int ar = wm * 64 + i * 16 + grp;
                al[i][0] = *(const uint32_t*)&sAl[ar][kk];
                al[i][1] = *(const uint32_t*)&sAl[ar + 8][kk];
                al[i][2] = *(const uint32_t*)&sAl[ar][kk + 8];
                al[i][3] = *(const uint32_t*)&sAl[ar + 8][kk + 8];
            }
            #pragma unroll
            for (int i = 0; i < 4; i++)
                #pragma unroll
                for (int j = 0; j < 4; j++) mma16816(c[i][j], al[i], bh[j]);
        }
    }

    #pragma unroll
    for (int i = 0; i < 4; i++) {
        #pragma unroll
        for (int j = 0; j < 4; j++) {
            int n0 = bn + wn * 32 + j * 8 + tig * 2;
            float2 bv = *(const float2*)(bias + n0);
            #pragma unroll
            for (int half = 0; half < 2; half++) {
                int m = bm + wm * 64 + i * 16 + grp + half * 8;
                float rx = c[i][j][half * 2 + 0] + bv.x;
                float ry = c[i][j][half * 2 + 1] + bv.y;
                if (mode == 0) {
                    *(float2*)(C + (size_t)m * N + n0) = make_float2(rx, ry);
                } else {
                    int sel = n0 >> 10, rem = n0 & 1023;
                    int h = rem >> 6, hd0 = rem & 63;
                    int b = m >> 11, s = m & 2047;
                    size_t bh_ = (size_t)b * HEADS + h;
                    if (sel == 0) {
                        __nv_bfloat162 lo2;
                        __nv_bfloat162 hi2 = split_pack(rx * 0.125f, ry * 0.125f, &lo2);
                        size_t off = (bh_ * SEQ + s) * HD + hd0;
                        *(__nv_bfloat162*)(qh + off) = hi2;
                        *(__nv_bfloat162*)(ql + off) = lo2;
                    } else if (sel == 1) {
                        __nv_bfloat162 lo2;
                        __nv_bfloat162 hi2 = split_pack(rx, ry, &lo2);
                        size_t off = (bh_ * SEQ + s) * HD + hd0;
                        *(__nv_bfloat162*)(kh + off) = hi2;
                        *(__nv_bfloat162*)(kl + off) = lo2;
                    } else {
                        __nv_bfloat162 lo2;
                        __nv_bfloat162 hi2 = split_pack(rx, ry, &lo2);
                        size_t o0 = (bh_ * HD + hd0) * SEQ + s;
                        size_t o1 = (bh_ * HD + hd0 + 1) * SEQ + s;
                        vth[o0] = hi2.x; vth[o1] = hi2.y;
                        vtl[o0] = lo2.x; vtl[o1] = lo2.y;
                    }
                }
            }
        }
    }
}

// ---------------------------------------------------------------------------
// HMMA flash attention. Grid (SEQ/64, B*H), 128 threads (4 warps x 16 q-rows).
// Key tiles of 64. Q in registers; S and P stay in registers; 3-pass hi/lo
// splits on both QK^T and PV. Output -> bf16 hi/lo [B,S,H*64].
// ---------------------------------------------------------------------------
#define KPITCH 72

__global__ __launch_bounds__(128, 3) void attn_hmma(
    const __nv_bfloat16* __restrict__ qh, const __nv_bfloat16* __restrict__ ql,
    const __nv_bfloat16* __restrict__ kh, const __nv_bfloat16* __restrict__ kl,
    const __nv_bfloat16* __restrict__ vth, const __nv_bfloat16* __restrict__ vtl,
    __nv_bfloat16* __restrict__ Ohi, __nv_bfloat16* __restrict__ Olo)
{
    __shared__ __nv_bfloat16 sKh[64][KPITCH], sKl[64][KPITCH];
    __shared__ __nv_bfloat16 sVh[64][KPITCH], sVl[64][KPITCH];

    const int tid  = threadIdx.x;
    const int wid  = tid >> 5;
    const int lane = tid & 31;
    const int grp  = lane >> 2;
    const int tig  = lane & 3;
    const int bh   = blockIdx.y;
    const int q0   = blockIdx.x * 64;

    // Q fragments (A-frags), 4 k-chunks of 16 over HD=64
    uint32_t qfh[4][4], qfl[4][4];
    {
        const __nv_bfloat16* Qh = qh + ((size_t)bh * SEQ + q0 + wid * 16) * HD;
        const __nv_bfloat16* Ql = ql + ((size_t)bh * SEQ + q0 + wid * 16) * HD;
        #pragma unroll
        for (int cc = 0; cc < 4; cc++) {
            int k0 = cc * 16 + 2 * tig;
            qfh[cc][0] = *(const uint32_t*)(Qh + grp * HD + k0);
            qfh[cc][1] = *(const uint32_t*)(Qh + (grp + 8) * HD + k0);
            qfh[cc][2] = *(const uint32_t*)(Qh + grp * HD + k0 + 8);
            qfh[cc][3] = *(const uint32_t*)(Qh + (grp + 8) * HD + k0 + 8);
            qfl[cc][0] = *(const uint32_t*)(Ql + grp * HD + k0);
            qfl[cc][1] = *(const uint32_t*)(Ql + (grp + 8) * HD + k0);
            qfl[cc][2] = *(const uint32_t*)(Ql + grp * HD + k0 + 8);
            qfl[cc][3] = *(const uint32_t*)(Ql + (grp + 8) * HD + k0 + 8);
        }
    }

    float o[8][4];
    #pragma unroll
    for (int j = 0; j < 8; j++)
        #pragma unroll
        for (int p = 0; p < 4; p++) o[j][p] = 0.f;
    float m0 = -INFINITY, m1 = -INFINITY, l0 = 0.f, l1 = 0.f;

    const __nv_bfloat16* Kbh = kh + (size_t)bh * SEQ * HD;
    const __nv_bfloat16* Kbl = kl + (size_t)bh * SEQ * HD;
    const __nv_bfloat16* Vbh = vth + (size_t)bh * HD * SEQ;
    const __nv_bfloat16* Vbl = vtl + (size_t)bh * HD * SEQ;

    for (int kt = 0; kt < SEQ / 64; kt++) {
        __syncthreads();
        #pragma unroll
        for (int i = 0; i < 4; i++) {
            int g = tid + i * 128;
            int r = g >> 3, ch = g & 7;
            *(uint4*)&sKh[r][ch * 8] = *(const uint4*)(Kbh + (size_t)(kt * 64 + r) * HD + ch * 8);
            *(uint4*)&sKl[r][ch * 8] = *(const uint4*)(Kbl + (size_t)(kt * 64 + r) * HD + ch * 8);
            *(uint4*)&sVh[r][ch * 8] = *(const uint4*)(Vbh + (size_t)r * SEQ + kt * 64 + ch * 8);
            *(uint4*)&sVl[r][ch * 8] = *(const uint4*)(Vbl + (size_t)r * SEQ + kt * 64 + ch * 8);
        }
        __syncthreads();

        // ---- S = Q K^T (3-pass) ----
        float s[8][4];
        #pragma unroll
        for (int j = 0; j < 8; j++)
            #pragma unroll
            for (int p = 0; p < 4; p++) s[j][p] = 0.f;
        #pragma unroll
        for (int j = 0; j < 8; j++) {
            #pragma unroll
            for (int cc = 0; cc < 4; cc++) {
                int kk = cc * 16 + 2 * tig;
                uint32_t kbh[2], kbl2[2];
                kbh[0] = *(const uint32_t*)&sKh[j * 8 + grp][kk];
                kbh[1] = *(const uint32_t*)&sKh[j * 8 + grp][kk + 8];
                kbl2[0] = *(const uint32_t*)&sKl[j * 8 + grp][kk];
                kbl2[1] = *(const uint32_t*)&sKl[j * 8 + grp][kk + 8];
                mma16816(s[j], qfh[cc], kbh);
                mma16816(s[j], qfh[cc], kbl2);
                mma16816(s[j], qfl[cc], kbh);
            }
        }

        // ---- online softmax ----
        float mx0 = -INFINITY, mx1 = -INFINITY;
        #pragma unroll
        for (int j = 0; j < 8; j++) {
            mx0 = fmaxf(mx0, fmaxf(s[j][0], s[j][1]));
            mx1 = fmaxf(mx1, fmaxf(s[j][2], s[j][3]));
        }
        mx0 = fmaxf(mx0, __shfl_xor_sync(0xffffffffu, mx0, 1));
        mx0 = fmaxf(mx0, __shfl_xor_sync(0xffffffffu, mx0, 2));
        mx1 = fmaxf(mx1, __shfl_xor_sync(0xffffffffu, mx1, 1));
        mx1 = fmaxf(mx1, __shfl_xor_sync(0xffffffffu, mx1, 2));
        float mn0 = fmaxf(m0, mx0), mn1 = fmaxf(m1, mx1);
        float a0 = __expf(m0 - mn0), a1 = __expf(m1 - mn1);
        m0 = mn0; m1 = mn1;

        uint32_t pfh[4][4], pfl[4][4];
        float ps0 = 0.f, ps1 = 0.f;
        #pragma unroll
        for (int j = 0; j < 8; j++) {
            float p0 = __expf(s[j][0] - m0);
            float p1 = __expf(s[j][1] - m0);
            float p2 = __expf(s[j][2] - m1);
            float p3 = __expf(s[j][3] - m1);
            ps0 += p0 + p1;
            ps1 += p2 + p3;
            int cc = j >> 1, half = j & 1;
            __nv_bfloat162 lo2a, lo2b;
            __nv_bfloat162 hi2a = split_pack(p0, p1, &lo2a);
            __nv_bfloat162 hi2b = split_pack(p2, p3, &lo2b);
            pfh[cc][0 + 2 * half] = *(uint32_t*)&hi2a;
            pfh[cc][1 + 2 * half] = *(uint32_t*)&hi2b;
            pfl[cc][0 + 2 * half] = *(uint32_t*)&lo2a;
            pfl[cc][1 + 2 * half] = *(uint32_t*)&lo2b;
        }
        ps0 += __shfl_xor_sync(0xffffffffu, ps0, 1);
        ps0 += __shfl_xor_sync(0xffffffffu, ps0, 2);
        ps1 += __shfl_xor_sync(0xffffffffu, ps1, 1);
        ps1 += __shfl_xor_sync(0xffffffffu, ps1, 2);
        l0 = l0 * a0 + ps0;
        l1 = l1 * a1 + ps1;

        #pragma unroll
        for (int j = 0; j < 8; j++) {
            o[j][0] *= a0; o[j][1] *= a0;
            o[j][2] *= a1; o[j][3] *= a1;
        }

        // ---- O += P V (3-pass) ----
        #pragma unroll
        for (int j = 0; j < 8; j++) {          // hd n-tile
            #pragma unroll
            for (int cc = 0; cc < 4; cc++) {   // key chunk
                int kk = cc * 16 + 2 * tig;
                uint32_t vbh[2], vbl2[2];
                vbh[0] = *(const uint32_t*)&sVh[j * 8 + grp][kk];
                vbh[1] = *(const uint32_t*)&sVh[j * 8 + grp][kk + 8];
                vbl2[0] = *(const uint32_t*)&sVl[j * 8 + grp][kk];
                vbl2[1] = *(const uint32_t*)&sVl[j * 8 + grp][kk + 8];
                mma16816(o[j], pfh[cc], vbh);
                mma16816(o[j], pfh[cc], vbl2);
                mma16816(o[j], pfl[cc], vbh);
            }
        }
    }

    // ---- epilogue: O / l, bf16 hi/lo split into [B,S,H*64] ----
    const int b = bh >> 4;
    const int h = bh & 15;
    float inv0 = 1.0f / l0, inv1 = 1.0f / l1;
    int s0 = q0 + wid * 16 + grp;
    int s1 = s0 + 8;
    #pragma unroll
    for (int j = 0; j < 8; j++) {
        int col = h * HD + j * 8 + 2 * tig;
        __nv_bfloat162 lo2;
        __nv_bfloat162 hi2 = split_pack(o[j][0] * inv0, o[j][1] * inv0, &lo2);
        size_t off0 = ((size_t)b * SEQ + s0) * HIDDEN + col;
        *(__nv_bfloat162*)(Ohi + off0) = hi2;
        *(__nv_bfloat162*)(Olo + off0) = lo2;
        hi2 = split_pack(o[j][2] * inv1, o[j][3] * inv1, &lo2);
        size_t off1 = ((size_t)b * SEQ + s1) * HIDDEN + col;
        *(__nv_bfloat162*)(Ohi + off1) = hi2;
        *(__nv_bfloat162*)(Olo + off1) = lo2;
    }
}

// ---------------------------------------------------------------------------
extern "C" void kernel_launch(void* const* d_in, const int* in_sizes, int n_in,
                              void* d_out, int out_size)
{
    const float* x     = (const float*)d_in[0];
    const float* W_qkv = (const float*)d_in[1];
    const float* b_qkv = (const float*)d_in[2];
    const float* W_out = (const float*)d_in[3];
    const float* b_out = (const float*)d_in[4];
    float* out = (float*)d_out;

    static __nv_bfloat16 *pah = nullptr, *pal, *pwqh, *pwql, *pwoh, *pwol;
    static __nv_bfloat16 *pqh, *pql, *pkh, *pkl, *pvth, *pvtl;
    if (!pah) {
        cudaGetSymbolAddress((void**)&pah, g_a_hi);
        cudaGetSymbolAddress((void**)&pal, g_a_lo);
        cudaGetSymbolAddress((void**)&pwqh, g_wq_hi);
        cudaGetSymbolAddress((void**)&pwql, g_wq_lo);
        cudaGetSymbolAddress((void**)&pwoh, g_wo_hi);
        cudaGetSymbolAddress((void**)&pwol, g_wo_lo);
        cudaGetSymbolAddress((void**)&pqh, g_qh);
        cudaGetSymbolAddress((void**)&pql, g_ql);
        cudaGetSymbolAddress((void**)&pkh, g_kh);
        cudaGetSymbolAddress((void**)&pkl, g_kl);
        cudaGetSymbolAddress((void**)&pvth, g_vth);
        cudaGetSymbolAddress((void**)&pvtl, g_vtl);
    }

    const int n4 = MTOT * HIDDEN / 4;

    // 1) split x; transpose+split weights
    split_kernel<<<n4 / 256, 256>>>(x, pah, pal, n4);
    {
        dim3 g(3 * HIDDEN / 32, HIDDEN / 32);
        tsplit_kernel<<<g, dim3(32, 8)>>>(W_qkv, pwqh, pwql, HIDDEN, 3 * HIDDEN);
    }
    {
        dim3 g(HIDDEN / 32, HIDDEN / 32);
        tsplit_kernel<<<g, dim3(32, 8)>>>(W_out, pwoh, pwol, HIDDEN, HIDDEN);
    }

    // 2) QKV projection (HMMA) -> bf16 hi/lo Q (scaled), K, V^T
    {
        dim3 g(3 * HIDDEN / 128, MTOT / 128);
        hmma_gemm<<<g, 256>>>(pah, pal, pwqh, pwql, b_qkv, nullptr,
                              pqh, pql, pkh, pkl, pvth, pvtl,
                              MTOT, 3 * HIDDEN, HIDDEN, 1);
    }

    // 3) HMMA flash attention -> bf16 hi/lo activations (reuse g_a)
    {
        dim3 g(SEQ / 64, BATCH * HEADS);
        attn_hmma<<<g, 128>>>(pqh, pql, pkh, pkl, pvth, pvtl, pah, pal);
    }

    // 4) output projection (HMMA) -> d_out
    {
        dim3 g(HIDDEN / 128, MTOT / 128);
        hmma_gemm<<<g, 256>>>(pah, pal, pwoh, pwol, b_out, out,
                              nullptr, nullptr, nullptr, nullptr, nullptr, nullptr,
                              MTOT, HIDDEN, HIDDEN, 0);
    }
}

// round 5
// speedup vs baseline: 2.4839x; 1.0757x over previous
#include <cuda_runtime.h>
#include <cuda_bf16.h>
#include <math.h>
#include <stdint.h>

#define HIDDEN 1024
#define HEADS  16
#define HD     64
#define BATCH  4
#define SEQ    2048
#define MTOT   (BATCH * SEQ)   // 8192

// ---------------- scratch (device globals; no allocs allowed) --------------
__device__ __nv_bfloat16 g_a_hi[MTOT * HIDDEN];
__device__ __nv_bfloat16 g_a_lo[MTOT * HIDDEN];
__device__ __nv_bfloat16 g_wq_hi[3 * HIDDEN * HIDDEN];
__device__ __nv_bfloat16 g_wq_lo[3 * HIDDEN * HIDDEN];
__device__ __nv_bfloat16 g_wo_hi[HIDDEN * HIDDEN];
__device__ __nv_bfloat16 g_wo_lo[HIDDEN * HIDDEN];
__device__ __nv_bfloat16 g_qh[BATCH * HEADS * SEQ * HD];
__device__ __nv_bfloat16 g_ql[BATCH * HEADS * SEQ * HD];
__device__ __nv_bfloat16 g_kh[BATCH * HEADS * SEQ * HD];
__device__ __nv_bfloat16 g_kl[BATCH * HEADS * SEQ * HD];
__device__ __nv_bfloat16 g_vth[BATCH * HEADS * HD * SEQ];
__device__ __nv_bfloat16 g_vtl[BATCH * HEADS * HD * SEQ];

// ---------------- cp.async helpers -----------------------------------------
__device__ __forceinline__ void cp_async16(uint32_t saddr, const void* gptr) {
    asm volatile("cp.async.ca.shared.global [%0], [%1], 16;"
                 :: "r"(saddr), "l"(gptr));
}
#define CP_COMMIT()  asm volatile("cp.async.commit_group;" ::: "memory")
#define CP_WAIT(n)   asm volatile("cp.async.wait_group %0;" :: "n"(n) : "memory")

// ---------------------------------------------------------------------------
__global__ __launch_bounds__(256) void split_kernel(
    const float* __restrict__ src, __nv_bfloat16* __restrict__ hi,
    __nv_bfloat16* __restrict__ lo, int n4)
{
    int i = blockIdx.x * blockDim.x + threadIdx.x;
    if (i >= n4) return;
    float4 v = ((const float4*)src)[i];
    float xs[4] = {v.x, v.y, v.z, v.w};
    __nv_bfloat16 h[4], l[4];
    #pragma unroll
    for (int j = 0; j < 4; j++) {
        h[j] = __float2bfloat16_rn(xs[j]);
        l[j] = __float2bfloat16_rn(xs[j] - __bfloat162float(h[j]));
    }
    ((__nv_bfloat162*)hi)[2 * i]     = __nv_bfloat162(h[0], h[1]);
    ((__nv_bfloat162*)hi)[2 * i + 1] = __nv_bfloat162(h[2], h[3]);
    ((__nv_bfloat162*)lo)[2 * i]     = __nv_bfloat162(l[0], l[1]);
    ((__nv_bfloat162*)lo)[2 * i + 1] = __nv_bfloat162(l[2], l[3]);
}

__global__ void tsplit_kernel(const float* __restrict__ W,
                              __nv_bfloat16* __restrict__ hi,
                              __nv_bfloat16* __restrict__ lo, int K, int N)
{
    __shared__ float t[32][33];
    int n0 = blockIdx.x * 32, k0 = blockIdx.y * 32;
    for (int r = threadIdx.y; r < 32; r += 8)
        t[r][threadIdx.x] = W[(size_t)(k0 + r) * N + n0 + threadIdx.x];
    __syncthreads();
    for (int r = threadIdx.y; r < 32; r += 8) {
        float x = t[threadIdx.x][r];
        __nv_bfloat16 h = __float2bfloat16_rn(x);
        __nv_bfloat16 l = __float2bfloat16_rn(x - __bfloat162float(h));
        size_t o = (size_t)(n0 + r) * K + k0 + threadIdx.x;
        hi[o] = h;
        lo[o] = l;
    }
}

// ---------------------------------------------------------------------------
__device__ __forceinline__ void mma16816(float* c, const uint32_t* a, const uint32_t* b)
{
    asm volatile(
        "mma.sync.aligned.m16n8k16.row.col.f32.bf16.bf16.f32 "
        "{%0,%1,%2,%3}, {%4,%5,%6,%7}, {%8,%9}, {%0,%1,%2,%3};"
        : "+f"(c[0]), "+f"(c[1]), "+f"(c[2]), "+f"(c[3])
        : "r"(a[0]), "r"(a[1]), "r"(a[2]), "r"(a[3]), "r"(b[0]), "r"(b[1]));
}

__device__ __forceinline__ __nv_bfloat162 split_pack(float x, float y,
                                                     __nv_bfloat162* lo)
{
    __nv_bfloat16 hx = __float2bfloat16_rn(x);
    __nv_bfloat16 hy = __float2bfloat16_rn(y);
    *lo = __nv_bfloat162(__float2bfloat16_rn(x - __bfloat162float(hx)),
                         __float2bfloat16_rn(y - __bfloat162float(hy)));
    return __nv_bfloat162(hx, hy);
}

// ---------------------------------------------------------------------------
// HMMA GEMM, cp.async 2-stage pipeline. Dynamic smem:
//   stage stride 40960 B; within stage: Ah=0, Al=10240, Bh=20480, Bl=30720
//   (rows of 40 bf16 = 80 B)
// ---------------------------------------------------------------------------
#define SPAD 40
#define GST  40960
#define GEMM_SMEM (2 * GST)

__global__ __launch_bounds__(256) void hmma_gemm(
    const __nv_bfloat16* __restrict__ Ahi, const __nv_bfloat16* __restrict__ Alo,
    const __nv_bfloat16* __restrict__ Bhi, const __nv_bfloat16* __restrict__ Blo,
    const float* __restrict__ bias, float* __restrict__ C,
    __nv_bfloat16* __restrict__ qh, __nv_bfloat16* __restrict__ ql,
    __nv_bfloat16* __restrict__ kh, __nv_bfloat16* __restrict__ kl,
    __nv_bfloat16* __restrict__ vth, __nv_bfloat16* __restrict__ vtl,
    int M, int N, int K, int mode)
{
    extern __shared__ char smem[];
    const uint32_t sbase = (uint32_t)__cvta_generic_to_shared(smem);

    const int tid  = threadIdx.x;
    const int wid  = tid >> 5;
    const int lane = tid & 31;
    const int grp  = lane >> 2;
    const int tig  = lane & 3;
    const int wm   = wid & 1;
    const int wn   = wid >> 1;
    const int bm   = blockIdx.y * 128;
    const int bn   = blockIdx.x * 128;
    const int NT   = K / 32;

    // per-thread load slots: 2 granules, each = row r, chunk ch (16B)
    const int r0 = tid >> 2,          ch0 = tid & 3;
    const int r1 = (tid + 256) >> 2,  ch1 = (tid + 256) & 3;

    float c[4][4][4];
    #pragma unroll
    for (int i = 0; i < 4; i++)
        #pragma unroll
        for (int j = 0; j < 4; j++)
            #pragma unroll
            for (int p = 0; p < 4; p++) c[i][j][p] = 0.f;

    auto issue_tile = [&](int kt, int stage) {
        const int k0 = kt * 32;
        const uint32_t st = sbase + stage * GST;
        {
            uint32_t so = (uint32_t)(r0 * SPAD + ch0 * 8) * 2;
            size_t ga = (size_t)(bm + r0) * K + k0 + ch0 * 8;
            size_t gb = (size_t)(bn + r0) * K + k0 + ch0 * 8;
            cp_async16(st + so,         Ahi + ga);
            cp_async16(st + 10240 + so, Alo + ga);
            cp_async16(st + 20480 + so, Bhi + gb);
            cp_async16(st + 30720 + so, Blo + gb);
        }
        {
            uint32_t so = (uint32_t)(r1 * SPAD + ch1 * 8) * 2;
            size_t ga = (size_t)(bm + r1) * K + k0 + ch1 * 8;
            size_t gb = (size_t)(bn + r1) * K + k0 + ch1 * 8;
            cp_async16(st + so,         Ahi + ga);
            cp_async16(st + 10240 + so, Alo + ga);
            cp_async16(st + 20480 + so, Bhi + gb);
            cp_async16(st + 30720 + so, Blo + gb);
        }
        CP_COMMIT();
    };

    issue_tile(0, 0);

    for (int kt = 0; kt < NT; kt++) {
        if (kt + 1 < NT) {
            issue_tile(kt + 1, (kt + 1) & 1);
            CP_WAIT(1);
        } else {
            CP_WAIT(0);
        }
        __syncthreads();

        const char* stp = smem + (kt & 1) * GST;
        const __nv_bfloat16* sAh = (const __nv_bfloat16*)(stp);
        const __nv_bfloat16* sAl = (const __nv_bfloat16*)(stp + 10240);
        const __nv_bfloat16* sBh = (const __nv_bfloat16*)(stp + 20480);
        const __nv_bfloat16* sBl = (const __nv_bfloat16*)(stp + 30720);

        #pragma unroll
        for (int ks = 0; ks < 2; ks++) {
            const int kk = ks * 16 + tig * 2;
            uint32_t ah[4][4], bh[4][2];
            #pragma unroll
            for (int i = 0; i < 4; i++) {
                int ar = wm * 64 + i * 16 + grp;
                ah[i][0] = *(const uint32_t*)&sAh[ar * SPAD + kk];
                ah[i][1] = *(const uint32_t*)&sAh[(ar + 8) * SPAD + kk];
                ah[i][2] = *(const uint32_t*)&sAh[ar * SPAD + kk + 8];
                ah[i][3] = *(const uint32_t*)&sAh[(ar + 8) * SPAD + kk + 8];
            }
            #pragma unroll
            for (int j = 0; j < 4; j++) {
                int br = wn * 32 + j * 8 + grp;
                bh[j][0] = *(const uint32_t*)&sBh[br * SPAD + kk];
                bh[j][1] = *(const uint32_t*)&sBh[br * SPAD + kk + 8];
            }
            #pragma unroll
            for (int i = 0; i < 4; i++)
                #pragma unroll
                for (int j = 0; j < 4; j++) mma16816(c[i][j], ah[i], bh[j]);
            uint32_t bl[4][2];
            #pragma unroll
            for (int j = 0; j < 4; j++) {
                int br = wn * 32 + j * 8 + grp;
                bl[j][0] = *(const uint32_t*)&sBl[br * SPAD + kk];
                bl[j][1] = *(const uint32_t*)&sBl[br * SPAD + kk + 8];
            }
            #pragma unroll
            for (int i = 0; i < 4; i++)
                #pragma unroll
                for (int j = 0; j < 4; j++) mma16816(c[i][j], ah[i], bl[j]);
            uint32_t al[4][4];
            #pragma unroll
            for (int i = 0; i < 4; i++) {
                int ar = wm * 64 + i * 16 + grp;
                al[i][0] = *(const uint32_t*)&sAl[ar * SPAD + kk];
                al[i][1] = *(const uint32_t*)&sAl[(ar + 8) * SPAD + kk];
                al[i][2] = *(const uint32_t*)&sAl[ar * SPAD + kk + 8];
                al[i][3] = *(const uint32_t*)&sAl[(ar + 8) * SPAD + kk + 8];
            }
            #pragma unroll
            for (int i = 0; i < 4; i++)
                #pragma unroll
                for (int j = 0; j < 4; j++) mma16816(c[i][j], al[i], bh[j]);
        }
        __syncthreads();
    }

    #pragma unroll
    for (int i = 0; i < 4; i++) {
        #pragma unroll
        for (int j = 0; j < 4; j++) {
            int n0 = bn + wn * 32 + j * 8 + tig * 2;
            float2 bv = *(const float2*)(bias + n0);
            #pragma unroll
            for (int half = 0; half < 2; half++) {
                int m = bm + wm * 64 + i * 16 + grp + half * 8;
                float rx = c[i][j][half * 2 + 0] + bv.x;
                float ry = c[i][j][half * 2 + 1] + bv.y;
                if (mode == 0) {
                    *(float2*)(C + (size_t)m * N + n0) = make_float2(rx, ry);
                } else {
                    int sel = n0 >> 10, rem = n0 & 1023;
                    int h = rem >> 6, hd0 = rem & 63;
                    int b = m >> 11, s = m & 2047;
                    size_t bh_ = (size_t)b * HEADS + h;
                    if (sel == 0) {
                        __nv_bfloat162 lo2;
                        __nv_bfloat162 hi2 = split_pack(rx * 0.125f, ry * 0.125f, &lo2);
                        size_t off = (bh_ * SEQ + s) * HD + hd0;
                        *(__nv_bfloat162*)(qh + off) = hi2;
                        *(__nv_bfloat162*)(ql + off) = lo2;
                    } else if (sel == 1) {
                        __nv_bfloat162 lo2;
                        __nv_bfloat162 hi2 = split_pack(rx, ry, &lo2);
                        size_t off = (bh_ * SEQ + s) * HD + hd0;
                        *(__nv_bfloat162*)(kh + off) = hi2;
                        *(__nv_bfloat162*)(kl + off) = lo2;
                    } else {
                        __nv_bfloat162 lo2;
                        __nv_bfloat162 hi2 = split_pack(rx, ry, &lo2);
                        size_t o0 = (bh_ * HD + hd0) * SEQ + s;
                        size_t o1 = (bh_ * HD + hd0 + 1) * SEQ + s;
                        vth[o0] = hi2.x; vth[o1] = hi2.y;
                        vtl[o0] = lo2.x; vtl[o1] = lo2.y;
                    }
                }
            }
        }
    }
}

// ---------------------------------------------------------------------------
// HMMA flash attention, cp.async 2-stage pipeline. Dynamic smem:
//   stage stride 36864 B; within stage: Kh=0, Kl=9216, Vh=18432, Vl=27648
//   (rows of 72 bf16 = 144 B)
// ---------------------------------------------------------------------------
#define KPITCH 72
#define AST    36864
#define ATTN_SMEM (2 * AST)

__global__ __launch_bounds__(128, 3) void attn_hmma(
    const __nv_bfloat16* __restrict__ qh, const __nv_bfloat16* __restrict__ ql,
    const __nv_bfloat16* __restrict__ kh, const __nv_bfloat16* __restrict__ kl,
    const __nv_bfloat16* __restrict__ vth, const __nv_bfloat16* __restrict__ vtl,
    __nv_bfloat16* __restrict__ Ohi, __nv_bfloat16* __restrict__ Olo)
{
    extern __shared__ char smem[];
    const uint32_t sbase = (uint32_t)__cvta_generic_to_shared(smem);

    const int tid  = threadIdx.x;
    const int wid  = tid >> 5;
    const int lane = tid & 31;
    const int grp  = lane >> 2;
    const int tig  = lane & 3;
    const int bh   = blockIdx.y;
    const int q0   = blockIdx.x * 64;

    const __nv_bfloat16* Kbh = kh + (size_t)bh * SEQ * HD;
    const __nv_bfloat16* Kbl = kl + (size_t)bh * SEQ * HD;
    const __nv_bfloat16* Vbh = vth + (size_t)bh * HD * SEQ;
    const __nv_bfloat16* Vbl = vtl + (size_t)bh * HD * SEQ;

    auto issue_tile = [&](int kt, int stage) {
        const uint32_t st = sbase + stage * AST;
        #pragma unroll
        for (int i = 0; i < 4; i++) {
            int g = tid + i * 128;
            int r = g >> 3, ch = g & 7;
            uint32_t so = (uint32_t)(r * KPITCH + ch * 8) * 2;
            cp_async16(st + so,         Kbh + (size_t)(kt * 64 + r) * HD + ch * 8);
            cp_async16(st + 9216 + so,  Kbl + (size_t)(kt * 64 + r) * HD + ch * 8);
            cp_async16(st + 18432 + so, Vbh + (size_t)r * SEQ + kt * 64 + ch * 8);
            cp_async16(st + 27648 + so, Vbl + (size_t)r * SEQ + kt * 64 + ch * 8);
        }
        CP_COMMIT();
    };

    issue_tile(0, 0);

    // Q fragments (loaded once from global, overlaps with first cp.async)
    uint32_t qfh[4][4], qfl[4][4];
    {
        const __nv_bfloat16* Qh = qh + ((size_t)bh * SEQ + q0 + wid * 16) * HD;
        const __nv_bfloat16* Ql = ql + ((size_t)bh * SEQ + q0 + wid * 16) * HD;
        #pragma unroll
        for (int cc = 0; cc < 4; cc++) {
            int k0 = cc * 16 + 2 * tig;
            qfh[cc][0] = *(const uint32_t*)(Qh + grp * HD + k0);
            qfh[cc][1] = *(const uint32_t*)(Qh + (grp + 8) * HD + k0);
            qfh[cc][2] = *(const uint32_t*)(Qh + grp * HD + k0 + 8);
            qfh[cc][3] = *(const uint32_t*)(Qh + (grp + 8) * HD + k0 + 8);
            qfl[cc][0] = *(const uint32_t*)(Ql + grp * HD + k0);
            qfl[cc][1] = *(const uint32_t*)(Ql + (grp + 8) * HD + k0);
            qfl[cc][2] = *(const uint32_t*)(Ql + grp * HD + k0 + 8);
            qfl[cc][3] = *(const uint32_t*)(Ql + (grp + 8) * HD + k0 + 8);
        }
    }

    float o[8][4];
    #pragma unroll
    for (int j = 0; j < 8; j++)
        #pragma unroll
        for (int p = 0; p < 4; p++) o[j][p] = 0.f;
    float m0 = -INFINITY, m1 = -INFINITY, l0 = 0.f, l1 = 0.f;

    const int NT = SEQ / 64;
    for (int kt = 0; kt < NT; kt++) {
        if (kt + 1 < NT) {
            issue_tile(kt + 1, (kt + 1) & 1);
            CP_WAIT(1);
        } else {
            CP_WAIT(0);
        }
        __syncthreads();

        const char* stp = smem + (kt & 1) * AST;
        const __nv_bfloat16* sKh = (const __nv_bfloat16*)(stp);
        const __nv_bfloat16* sKl = (const __nv_bfloat16*)(stp + 9216);
        const __nv_bfloat16* sVh = (const __nv_bfloat16*)(stp + 18432);
        const __nv_bfloat16* sVl = (const __nv_bfloat16*)(stp + 27648);

        // ---- S = Q K^T (3-pass) ----
        float s[8][4];
        #pragma unroll
        for (int j = 0; j < 8; j++)
            #pragma unroll
            for (int p = 0; p < 4; p++) s[j][p] = 0.f;
        #pragma unroll
        for (int j = 0; j < 8; j++) {
            #pragma unroll
            for (int cc = 0; cc < 4; cc++) {
                int kk = cc * 16 + 2 * tig;
                uint32_t kbh[2], kbl2[2];
                kbh[0]  = *(const uint32_t*)&sKh[(j * 8 + grp) * KPITCH + kk];
                kbh[1]  = *(const uint32_t*)&sKh[(j * 8 + grp) * KPITCH + kk + 8];
                kbl2[0] = *(const uint32_t*)&sKl[(j * 8 + grp) * KPITCH + kk];
                kbl2[1] = *(const uint32_t*)&sKl[(j * 8 + grp) * KPITCH + kk + 8];
                mma16816(s[j], qfh[cc], kbh);
                mma16816(s[j], qfh[cc], kbl2);
                mma16816(s[j], qfl[cc], kbh);
            }
        }

        // ---- online softmax ----
        float mx0 = -INFINITY, mx1 = -INFINITY;
        #pragma unroll
        for (int j = 0; j < 8; j++) {
            mx0 = fmaxf(mx0, fmaxf(s[j][0], s[j][1]));
            mx1 = fmaxf(mx1, fmaxf(s[j][2], s[j][3]));
        }
        mx0 = fmaxf(mx0, __shfl_xor_sync(0xffffffffu, mx0, 1));
        mx0 = fmaxf(mx0, __shfl_xor_sync(0xffffffffu, mx0, 2));
        mx1 = fmaxf(mx1, __shfl_xor_sync(0xffffffffu, mx1, 1));
        mx1 = fmaxf(mx1, __shfl_xor_sync(0xffffffffu, mx1, 2));
        float mn0 = fmaxf(m0, mx0), mn1 = fmaxf(m1, mx1);
        float a0 = __expf(m0 - mn0), a1 = __expf(m1 - mn1);
        m0 = mn0; m1 = mn1;

        uint32_t pfh[4][4], pfl[4][4];
        float ps0 = 0.f, ps1 = 0.f;
        #pragma unroll
        for (int j = 0; j < 8; j++) {
            float p0 = __expf(s[j][0] - m0);
            float p1 = __expf(s[j][1] - m0);
            float p2 = __expf(s[j][2] - m1);
            float p3 = __expf(s[j][3] - m1);
            ps0 += p0 + p1;
            ps1 += p2 + p3;
            int cc = j >> 1, half = j & 1;
            __nv_bfloat162 lo2a, lo2b;
            __nv_bfloat162 hi2a = split_pack(p0, p1, &lo2a);
            __nv_bfloat162 hi2b = split_pack(p2, p3, &lo2b);
            pfh[cc][0 + 2 * half] = *(uint32_t*)&hi2a;
            pfh[cc][1 + 2 * half] = *(uint32_t*)&hi2b;
            pfl[cc][0 + 2 * half] = *(uint32_t*)&lo2a;
            pfl[cc][1 + 2 * half] = *(uint32_t*)&lo2b;
        }
        ps0 += __shfl_xor_sync(0xffffffffu, ps0, 1);
        ps0 += __shfl_xor_sync(0xffffffffu, ps0, 2);
        ps1 += __shfl_xor_sync(0xffffffffu, ps1, 1);
        ps1 += __shfl_xor_sync(0xffffffffu, ps1, 2);
        l0 = l0 * a0 + ps0;
        l1 = l1 * a1 + ps1;

        #pragma unroll
        for (int j = 0; j < 8; j++) {
            o[j][0] *= a0; o[j][1] *= a0;
            o[j][2] *= a1; o[j][3] *= a1;
        }

        // ---- O += P V (3-pass) ----
        #pragma unroll
        for (int j = 0; j < 8; j++) {
            #pragma unroll
            for (int cc = 0; cc < 4; cc++) {
                int kk = cc * 16 + 2 * tig;
                uint32_t vbh[2], vbl2[2];
                vbh[0]  = *(const uint32_t*)&sVh[(j * 8 + grp) * KPITCH + kk];
                vbh[1]  = *(const uint32_t*)&sVh[(j * 8 + grp) * KPITCH + kk + 8];
                vbl2[0] = *(const uint32_t*)&sVl[(j * 8 + grp) * KPITCH + kk];
                vbl2[1] = *(const uint32_t*)&sVl[(j * 8 + grp) * KPITCH + kk + 8];
                mma16816(o[j], pfh[cc], vbh);
                mma16816(o[j], pfh[cc], vbl2);
                mma16816(o[j], pfl[cc], vbh);
            }
        }
        __syncthreads();
    }

    // ---- epilogue ----
    const int b = bh >> 4;
    const int h = bh & 15;
    float inv0 = 1.0f / l0, inv1 = 1.0f / l1;
    int s0 = q0 + wid * 16 + grp;
    int s1 = s0 + 8;
    #pragma unroll
    for (int j = 0; j < 8; j++) {
        int col = h * HD + j * 8 + 2 * tig;
        __nv_bfloat162 lo2;
        __nv_bfloat162 hi2 = split_pack(o[j][0] * inv0, o[j][1] * inv0, &lo2);
        size_t off0 = ((size_t)b * SEQ + s0) * HIDDEN + col;
        *(__nv_bfloat162*)(Ohi + off0) = hi2;
        *(__nv_bfloat162*)(Olo + off0) = lo2;
        hi2 = split_pack(o[j][2] * inv1, o[j][3] * inv1, &lo2);
        size_t off1 = ((size_t)b * SEQ + s1) * HIDDEN + col;
        *(__nv_bfloat162*)(Ohi + off1) = hi2;
        *(__nv_bfloat162*)(Olo + off1) = lo2;
    }
}

// ---------------------------------------------------------------------------
extern "C" void kernel_launch(void* const* d_in, const int* in_sizes, int n_in,
                              void* d_out, int out_size)
{
    const float* x     = (const float*)d_in[0];
    const float* W_qkv = (const float*)d_in[1];
    const float* b_qkv = (const float*)d_in[2];
    const float* W_out = (const float*)d_in[3];
    const float* b_out = (const float*)d_in[4];
    float* out = (float*)d_out;

    static __nv_bfloat16 *pah = nullptr, *pal, *pwqh, *pwql, *pwoh, *pwol;
    static __nv_bfloat16 *pqh, *pql, *pkh, *pkl, *pvth, *pvtl;
    if (!pah) {
        cudaGetSymbolAddress((void**)&pah, g_a_hi);
        cudaGetSymbolAddress((void**)&pal, g_a_lo);
        cudaGetSymbolAddress((void**)&pwqh, g_wq_hi);
        cudaGetSymbolAddress((void**)&pwql, g_wq_lo);
        cudaGetSymbolAddress((void**)&pwoh, g_wo_hi);
        cudaGetSymbolAddress((void**)&pwol, g_wo_lo);
        cudaGetSymbolAddress((void**)&pqh, g_qh);
        cudaGetSymbolAddress((void**)&pql, g_ql);
        cudaGetSymbolAddress((void**)&pkh, g_kh);
        cudaGetSymbolAddress((void**)&pkl, g_kl);
        cudaGetSymbolAddress((void**)&pvth, g_vth);
        cudaGetSymbolAddress((void**)&pvtl, g_vtl);
        cudaFuncSetAttribute(hmma_gemm, cudaFuncAttributeMaxDynamicSharedMemorySize, GEMM_SMEM);
        cudaFuncSetAttribute(attn_hmma, cudaFuncAttributeMaxDynamicSharedMemorySize, ATTN_SMEM);
    }

    const int n4 = MTOT * HIDDEN / 4;

    split_kernel<<<n4 / 256, 256>>>(x, pah, pal, n4);
    {
        dim3 g(3 * HIDDEN / 32, HIDDEN / 32);
        tsplit_kernel<<<g, dim3(32, 8)>>>(W_qkv, pwqh, pwql, HIDDEN, 3 * HIDDEN);
    }
    {
        dim3 g(HIDDEN / 32, HIDDEN / 32);
        tsplit_kernel<<<g, dim3(32, 8)>>>(W_out, pwoh, pwol, HIDDEN, HIDDEN);
    }

    {
        dim3 g(3 * HIDDEN / 128, MTOT / 128);
        hmma_gemm<<<g, 256, GEMM_SMEM>>>(pah, pal, pwqh, pwql, b_qkv, nullptr,
                                         pqh, pql, pkh, pkl, pvth, pvtl,
                                         MTOT, 3 * HIDDEN, HIDDEN, 1);
    }

    {
        dim3 g(SEQ / 64, BATCH * HEADS);
        attn_hmma<<<g, 128, ATTN_SMEM>>>(pqh, pql, pkh, pkl, pvth, pvtl, pah, pal);
    }

    {
        dim3 g(HIDDEN / 128, MTOT / 128);
        hmma_gemm<<<g, 256, GEMM_SMEM>>>(pah, pal, pwoh, pwol, b_out, out,
                                         nullptr, nullptr, nullptr, nullptr, nullptr, nullptr,
                                         MTOT, HIDDEN, HIDDEN, 0);
    }
}

// round 6
// speedup vs baseline: 2.6840x; 1.0806x over previous
#include <cuda_runtime.h>
#include <cuda_bf16.h>
#include <math.h>
#include <stdint.h>

#define HIDDEN 1024
#define HEADS  16
#define HD     64
#define BATCH  4
#define SEQ    2048
#define MTOT   (BATCH * SEQ)   // 8192

// ---------------- scratch (device globals; no allocs allowed) --------------
__device__ __nv_bfloat16 g_a_hi[MTOT * HIDDEN];
__device__ __nv_bfloat16 g_a_lo[MTOT * HIDDEN];
__device__ __nv_bfloat16 g_wq_hi[3 * HIDDEN * HIDDEN];
__device__ __nv_bfloat16 g_wq_lo[3 * HIDDEN * HIDDEN];
__device__ __nv_bfloat16 g_wo_hi[HIDDEN * HIDDEN];
__device__ __nv_bfloat16 g_wo_lo[HIDDEN * HIDDEN];
__device__ __nv_bfloat16 g_qh[BATCH * HEADS * SEQ * HD];
__device__ __nv_bfloat16 g_ql[BATCH * HEADS * SEQ * HD];
__device__ __nv_bfloat16 g_kh[BATCH * HEADS * SEQ * HD];
__device__ __nv_bfloat16 g_kl[BATCH * HEADS * SEQ * HD];
__device__ __nv_bfloat16 g_vth[BATCH * HEADS * HD * SEQ];
__device__ __nv_bfloat16 g_vtl[BATCH * HEADS * HD * SEQ];

// ---------------- cp.async helpers -----------------------------------------
__device__ __forceinline__ void cp_async16(uint32_t saddr, const void* gptr) {
    asm volatile("cp.async.ca.shared.global [%0], [%1], 16;"
                 :: "r"(saddr), "l"(gptr));
}
#define CP_COMMIT()  asm volatile("cp.async.commit_group;" ::: "memory")
#define CP_WAIT(n)   asm volatile("cp.async.wait_group %0;" :: "n"(n) : "memory")

// ---------------------------------------------------------------------------
__global__ __launch_bounds__(256) void split_kernel(
    const float* __restrict__ src, __nv_bfloat16* __restrict__ hi,
    __nv_bfloat16* __restrict__ lo, int n4)
{
    int i = blockIdx.x * blockDim.x + threadIdx.x;
    if (i >= n4) return;
    float4 v = ((const float4*)src)[i];
    float xs[4] = {v.x, v.y, v.z, v.w};
    __nv_bfloat16 h[4], l[4];
    #pragma unroll
    for (int j = 0; j < 4; j++) {
        h[j] = __float2bfloat16_rn(xs[j]);
        l[j] = __float2bfloat16_rn(xs[j] - __bfloat162float(h[j]));
    }
    ((__nv_bfloat162*)hi)[2 * i]     = __nv_bfloat162(h[0], h[1]);
    ((__nv_bfloat162*)hi)[2 * i + 1] = __nv_bfloat162(h[2], h[3]);
    ((__nv_bfloat162*)lo)[2 * i]     = __nv_bfloat162(l[0], l[1]);
    ((__nv_bfloat162*)lo)[2 * i + 1] = __nv_bfloat162(l[2], l[3]);
}

__global__ void tsplit_kernel(const float* __restrict__ W,
                              __nv_bfloat16* __restrict__ hi,
                              __nv_bfloat16* __restrict__ lo, int K, int N)
{
    __shared__ float t[32][33];
    int n0 = blockIdx.x * 32, k0 = blockIdx.y * 32;
    for (int r = threadIdx.y; r < 32; r += 8)
        t[r][threadIdx.x] = W[(size_t)(k0 + r) * N + n0 + threadIdx.x];
    __syncthreads();
    for (int r = threadIdx.y; r < 32; r += 8) {
        float x = t[threadIdx.x][r];
        __nv_bfloat16 h = __float2bfloat16_rn(x);
        __nv_bfloat16 l = __float2bfloat16_rn(x - __bfloat162float(h));
        size_t o = (size_t)(n0 + r) * K + k0 + threadIdx.x;
        hi[o] = h;
        lo[o] = l;
    }
}

// ---------------------------------------------------------------------------
__device__ __forceinline__ void mma16816(float* c, const uint32_t* a, const uint32_t* b)
{
    asm volatile(
        "mma.sync.aligned.m16n8k16.row.col.f32.bf16.bf16.f32 "
        "{%0,%1,%2,%3}, {%4,%5,%6,%7}, {%8,%9}, {%0,%1,%2,%3};"
        : "+f"(c[0]), "+f"(c[1]), "+f"(c[2]), "+f"(c[3])
        : "r"(a[0]), "r"(a[1]), "r"(a[2]), "r"(a[3]), "r"(b[0]), "r"(b[1]));
}

__device__ __forceinline__ __nv_bfloat162 split_pack(float x, float y,
                                                     __nv_bfloat162* lo)
{
    __nv_bfloat16 hx = __float2bfloat16_rn(x);
    __nv_bfloat16 hy = __float2bfloat16_rn(y);
    *lo = __nv_bfloat162(__float2bfloat16_rn(x - __bfloat162float(hx)),
                         __float2bfloat16_rn(y - __bfloat162float(hy)));
    return __nv_bfloat162(hx, hy);
}

// ---------------------------------------------------------------------------
// HMMA GEMM, cp.async 2-stage pipeline, 2 CTAs/SM.
// ---------------------------------------------------------------------------
#define SPAD 40
#define GST  40960
#define GEMM_SMEM (2 * GST)

__global__ __launch_bounds__(256, 2) void hmma_gemm(
    const __nv_bfloat16* __restrict__ Ahi, const __nv_bfloat16* __restrict__ Alo,
    const __nv_bfloat16* __restrict__ Bhi, const __nv_bfloat16* __restrict__ Blo,
    const float* __restrict__ bias, float* __restrict__ C,
    __nv_bfloat16* __restrict__ qh, __nv_bfloat16* __restrict__ ql,
    __nv_bfloat16* __restrict__ kh, __nv_bfloat16* __restrict__ kl,
    __nv_bfloat16* __restrict__ vth, __nv_bfloat16* __restrict__ vtl,
    int M, int N, int K, int mode)
{
    extern __shared__ char smem[];
    const uint32_t sbase = (uint32_t)__cvta_generic_to_shared(smem);

    const int tid  = threadIdx.x;
    const int wid  = tid >> 5;
    const int lane = tid & 31;
    const int grp  = lane >> 2;
    const int tig  = lane & 3;
    const int wm   = wid & 1;
    const int wn   = wid >> 1;
    const int bm   = blockIdx.y * 128;
    const int bn   = blockIdx.x * 128;
    const int NT   = K / 32;

    const int r0 = tid >> 2,          ch0 = tid & 3;
    const int r1 = (tid + 256) >> 2,  ch1 = (tid + 256) & 3;

    float c[4][4][4];
    #pragma unroll
    for (int i = 0; i < 4; i++)
        #pragma unroll
        for (int j = 0; j < 4; j++)
            #pragma unroll
            for (int p = 0; p < 4; p++) c[i][j][p] = 0.f;

    auto issue_tile = [&](int kt, int stage) {
        const int k0 = kt * 32;
        const uint32_t st = sbase + stage * GST;
        {
            uint32_t so = (uint32_t)(r0 * SPAD + ch0 * 8) * 2;
            size_t ga = (size_t)(bm + r0) * K + k0 + ch0 * 8;
            size_t gb = (size_t)(bn + r0) * K + k0 + ch0 * 8;
            cp_async16(st + so,         Ahi + ga);
            cp_async16(st + 10240 + so, Alo + ga);
            cp_async16(st + 20480 + so, Bhi + gb);
            cp_async16(st + 30720 + so, Blo + gb);
        }
        {
            uint32_t so = (uint32_t)(r1 * SPAD + ch1 * 8) * 2;
            size_t ga = (size_t)(bm + r1) * K + k0 + ch1 * 8;
            size_t gb = (size_t)(bn + r1) * K + k0 + ch1 * 8;
            cp_async16(st + so,         Ahi + ga);
            cp_async16(st + 10240 + so, Alo + ga);
            cp_async16(st + 20480 + so, Bhi + gb);
            cp_async16(st + 30720 + so, Blo + gb);
        }
        CP_COMMIT();
    };

    issue_tile(0, 0);

    for (int kt = 0; kt < NT; kt++) {
        if (kt + 1 < NT) {
            issue_tile(kt + 1, (kt + 1) & 1);
            CP_WAIT(1);
        } else {
            CP_WAIT(0);
        }
        __syncthreads();

        const char* stp = smem + (kt & 1) * GST;
        const __nv_bfloat16* sAh = (const __nv_bfloat16*)(stp);
        const __nv_bfloat16* sAl = (const __nv_bfloat16*)(stp + 10240);
        const __nv_bfloat16* sBh = (const __nv_bfloat16*)(stp + 20480);
        const __nv_bfloat16* sBl = (const __nv_bfloat16*)(stp + 30720);

        #pragma unroll
        for (int ks = 0; ks < 2; ks++) {
            const int kk = ks * 16 + tig * 2;
            uint32_t ah[4][4], bh[4][2];
            #pragma unroll
            for (int i = 0; i < 4; i++) {
                int ar = wm * 64 + i * 16 + grp;
                ah[i][0] = *(const uint32_t*)&sAh[ar * SPAD + kk];
                ah[i][1] = *(const uint32_t*)&sAh[(ar + 8) * SPAD + kk];
                ah[i][2] = *(const uint32_t*)&sAh[ar * SPAD + kk + 8];
                ah[i][3] = *(const uint32_t*)&sAh[(ar + 8) * SPAD + kk + 8];
            }
            #pragma unroll
            for (int j = 0; j < 4; j++) {
                int br = wn * 32 + j * 8 + grp;
                bh[j][0] = *(const uint32_t*)&sBh[br * SPAD + kk];
                bh[j][1] = *(const uint32_t*)&sBh[br * SPAD + kk + 8];
            }
            #pragma unroll
            for (int i = 0; i < 4; i++)
                #pragma unroll
                for (int j = 0; j < 4; j++) mma16816(c[i][j], ah[i], bh[j]);
            uint32_t bl[4][2];
            #pragma unroll
            for (int j = 0; j < 4; j++) {
                int br = wn * 32 + j * 8 + grp;
                bl[j][0] = *(const uint32_t*)&sBl[br * SPAD + kk];
                bl[j][1] = *(const uint32_t*)&sBl[br * SPAD + kk + 8];
            }
            #pragma unroll
            for (int i = 0; i < 4; i++)
                #pragma unroll
                for (int j = 0; j < 4; j++) mma16816(c[i][j], ah[i], bl[j]);
            uint32_t al[4][4];
            #pragma unroll
            for (int i = 0; i < 4; i++) {
                int ar = wm * 64 + i * 16 + grp;
                al[i][0] = *(const uint32_t*)&sAl[ar * SPAD + kk];
                al[i][1] = *(const uint32_t*)&sAl[(ar + 8) * SPAD + kk];
                al[i][2] = *(const uint32_t*)&sAl[ar * SPAD + kk + 8];
                al[i][3] = *(const uint32_t*)&sAl[(ar + 8) * SPAD + kk + 8];
            }
            #pragma unroll
            for (int i = 0; i < 4; i++)
                #pragma unroll
                for (int j = 0; j < 4; j++) mma16816(c[i][j], al[i], bh[j]);
        }
        __syncthreads();
    }

    #pragma unroll
    for (int i = 0; i < 4; i++) {
        #pragma unroll
        for (int j = 0; j < 4; j++) {
            int n0 = bn + wn * 32 + j * 8 + tig * 2;
            float2 bv = *(const float2*)(bias + n0);
            #pragma unroll
            for (int half = 0; half < 2; half++) {
                int m = bm + wm * 64 + i * 16 + grp + half * 8;
                float rx = c[i][j][half * 2 + 0] + bv.x;
                float ry = c[i][j][half * 2 + 1] + bv.y;
                if (mode == 0) {
                    *(float2*)(C + (size_t)m * N + n0) = make_float2(rx, ry);
                } else {
                    int sel = n0 >> 10, rem = n0 & 1023;
                    int h = rem >> 6, hd0 = rem & 63;
                    int b = m >> 11, s = m & 2047;
                    size_t bh_ = (size_t)b * HEADS + h;
                    if (sel == 0) {
                        __nv_bfloat162 lo2;
                        __nv_bfloat162 hi2 = split_pack(rx * 0.125f, ry * 0.125f, &lo2);
                        size_t off = (bh_ * SEQ + s) * HD + hd0;
                        *(__nv_bfloat162*)(qh + off) = hi2;
                        *(__nv_bfloat162*)(ql + off) = lo2;
                    } else if (sel == 1) {
                        __nv_bfloat162 lo2;
                        __nv_bfloat162 hi2 = split_pack(rx, ry, &lo2);
                        size_t off = (bh_ * SEQ + s) * HD + hd0;
                        *(__nv_bfloat162*)(kh + off) = hi2;
                        *(__nv_bfloat162*)(kl + off) = lo2;
                    } else {
                        __nv_bfloat162 lo2;
                        __nv_bfloat162 hi2 = split_pack(rx, ry, &lo2);
                        size_t o0 = (bh_ * HD + hd0) * SEQ + s;
                        size_t o1 = (bh_ * HD + hd0 + 1) * SEQ + s;
                        vth[o0] = hi2.x; vth[o1] = hi2.y;
                        vtl[o0] = lo2.x; vtl[o1] = lo2.y;
                    }
                }
            }
        }
    }
}

// ---------------------------------------------------------------------------
// HMMA flash attention: 128 q-rows per CTA (8 warps, 256 thr), 64-key tiles,
// cp.async 2-stage, 2 CTAs/SM. Each K/V tile now serves 128 q-rows.
// ---------------------------------------------------------------------------
#define KPITCH 72
#define AST    36864
#define ATTN_SMEM (2 * AST)

__global__ __launch_bounds__(256, 2) void attn_hmma(
    const __nv_bfloat16* __restrict__ qh, const __nv_bfloat16* __restrict__ ql,
    const __nv_bfloat16* __restrict__ kh, const __nv_bfloat16* __restrict__ kl,
    const __nv_bfloat16* __restrict__ vth, const __nv_bfloat16* __restrict__ vtl,
    __nv_bfloat16* __restrict__ Ohi, __nv_bfloat16* __restrict__ Olo)
{
    extern __shared__ char smem[];
    const uint32_t sbase = (uint32_t)__cvta_generic_to_shared(smem);

    const int tid  = threadIdx.x;
    const int wid  = tid >> 5;          // 0..7, each owns 16 q-rows
    const int lane = tid & 31;
    const int grp  = lane >> 2;
    const int tig  = lane & 3;
    const int bh   = blockIdx.y;
    const int q0   = blockIdx.x * 128;

    const __nv_bfloat16* Kbh = kh + (size_t)bh * SEQ * HD;
    const __nv_bfloat16* Kbl = kl + (size_t)bh * SEQ * HD;
    const __nv_bfloat16* Vbh = vth + (size_t)bh * HD * SEQ;
    const __nv_bfloat16* Vbl = vtl + (size_t)bh * HD * SEQ;

    auto issue_tile = [&](int kt, int stage) {
        const uint32_t st = sbase + stage * AST;
        #pragma unroll
        for (int i = 0; i < 2; i++) {
            int g = tid + i * 256;          // 0..511
            int r = g >> 3, ch = g & 7;
            uint32_t so = (uint32_t)(r * KPITCH + ch * 8) * 2;
            cp_async16(st + so,         Kbh + (size_t)(kt * 64 + r) * HD + ch * 8);
            cp_async16(st + 9216 + so,  Kbl + (size_t)(kt * 64 + r) * HD + ch * 8);
            cp_async16(st + 18432 + so, Vbh + (size_t)r * SEQ + kt * 64 + ch * 8);
            cp_async16(st + 27648 + so, Vbl + (size_t)r * SEQ + kt * 64 + ch * 8);
        }
        CP_COMMIT();
    };

    issue_tile(0, 0);

    uint32_t qfh[4][4], qfl[4][4];
    {
        const __nv_bfloat16* Qh = qh + ((size_t)bh * SEQ + q0 + wid * 16) * HD;
        const __nv_bfloat16* Ql = ql + ((size_t)bh * SEQ + q0 + wid * 16) * HD;
        #pragma unroll
        for (int cc = 0; cc < 4; cc++) {
            int k0 = cc * 16 + 2 * tig;
            qfh[cc][0] = *(const uint32_t*)(Qh + grp * HD + k0);
            qfh[cc][1] = *(const uint32_t*)(Qh + (grp + 8) * HD + k0);
            qfh[cc][2] = *(const uint32_t*)(Qh + grp * HD + k0 + 8);
            qfh[cc][3] = *(const uint32_t*)(Qh + (grp + 8) * HD + k0 + 8);
            qfl[cc][0] = *(const uint32_t*)(Ql + grp * HD + k0);
            qfl[cc][1] = *(const uint32_t*)(Ql + (grp + 8) * HD + k0);
            qfl[cc][2] = *(const uint32_t*)(Ql + grp * HD + k0 + 8);
            qfl[cc][3] = *(const uint32_t*)(Ql + (grp + 8) * HD + k0 + 8);
        }
    }

    float o[8][4];
    #pragma unroll
    for (int j = 0; j < 8; j++)
        #pragma unroll
        for (int p = 0; p < 4; p++) o[j][p] = 0.f;
    float m0 = -INFINITY, m1 = -INFINITY, l0 = 0.f, l1 = 0.f;

    const int NT = SEQ / 64;
    for (int kt = 0; kt < NT; kt++) {
        if (kt + 1 < NT) {
            issue_tile(kt + 1, (kt + 1) & 1);
            CP_WAIT(1);
        } else {
            CP_WAIT(0);
        }
        __syncthreads();

        const char* stp = smem + (kt & 1) * AST;
        const __nv_bfloat16* sKh = (const __nv_bfloat16*)(stp);
        const __nv_bfloat16* sKl = (const __nv_bfloat16*)(stp + 9216);
        const __nv_bfloat16* sVh = (const __nv_bfloat16*)(stp + 18432);
        const __nv_bfloat16* sVl = (const __nv_bfloat16*)(stp + 27648);

        // ---- S = Q K^T (3-pass) ----
        float s[8][4];
        #pragma unroll
        for (int j = 0; j < 8; j++)
            #pragma unroll
            for (int p = 0; p < 4; p++) s[j][p] = 0.f;
        #pragma unroll
        for (int j = 0; j < 8; j++) {
            #pragma unroll
            for (int cc = 0; cc < 4; cc++) {
                int kk = cc * 16 + 2 * tig;
                uint32_t kbh[2], kbl2[2];
                kbh[0]  = *(const uint32_t*)&sKh[(j * 8 + grp) * KPITCH + kk];
                kbh[1]  = *(const uint32_t*)&sKh[(j * 8 + grp) * KPITCH + kk + 8];
                kbl2[0] = *(const uint32_t*)&sKl[(j * 8 + grp) * KPITCH + kk];
                kbl2[1] = *(const uint32_t*)&sKl[(j * 8 + grp) * KPITCH + kk + 8];
                mma16816(s[j], qfh[cc], kbh);
                mma16816(s[j], qfh[cc], kbl2);
                mma16816(s[j], qfl[cc], kbh);
            }
        }

        // ---- online softmax ----
        float mx0 = -INFINITY, mx1 = -INFINITY;
        #pragma unroll
        for (int j = 0; j < 8; j++) {
            mx0 = fmaxf(mx0, fmaxf(s[j][0], s[j][1]));
            mx1 = fmaxf(mx1, fmaxf(s[j][2], s[j][3]));
        }
        mx0 = fmaxf(mx0, __shfl_xor_sync(0xffffffffu, mx0, 1));
        mx0 = fmaxf(mx0, __shfl_xor_sync(0xffffffffu, mx0, 2));
        mx1 = fmaxf(mx1, __shfl_xor_sync(0xffffffffu, mx1, 1));
        mx1 = fmaxf(mx1, __shfl_xor_sync(0xffffffffu, mx1, 2));
        float mn0 = fmaxf(m0, mx0), mn1 = fmaxf(m1, mx1);
        float a0 = __expf(m0 - mn0), a1 = __expf(m1 - mn1);
        m0 = mn0; m1 = mn1;

        uint32_t pfh[4][4], pfl[4][4];
        float ps0 = 0.f, ps1 = 0.f;
        #pragma unroll
        for (int j = 0; j < 8; j++) {
            float p0 = __expf(s[j][0] - m0);
            float p1 = __expf(s[j][1] - m0);
            float p2 = __expf(s[j][2] - m1);
            float p3 = __expf(s[j][3] - m1);
            ps0 += p0 + p1;
            ps1 += p2 + p3;
            int cc = j >> 1, half = j & 1;
            __nv_bfloat162 lo2a, lo2b;
            __nv_bfloat162 hi2a = split_pack(p0, p1, &lo2a);
            __nv_bfloat162 hi2b = split_pack(p2, p3, &lo2b);
            pfh[cc][0 + 2 * half] = *(uint32_t*)&hi2a;
            pfh[cc][1 + 2 * half] = *(uint32_t*)&hi2b;
            pfl[cc][0 + 2 * half] = *(uint32_t*)&lo2a;
            pfl[cc][1 + 2 * half] = *(uint32_t*)&lo2b;
        }
        ps0 += __shfl_xor_sync(0xffffffffu, ps0, 1);
        ps0 += __shfl_xor_sync(0xffffffffu, ps0, 2);
        ps1 += __shfl_xor_sync(0xffffffffu, ps1, 1);
        ps1 += __shfl_xor_sync(0xffffffffu, ps1, 2);
        l0 = l0 * a0 + ps0;
        l1 = l1 * a1 + ps1;

        #pragma unroll
        for (int j = 0; j < 8; j++) {
            o[j][0] *= a0; o[j][1] *= a0;
            o[j][2] *= a1; o[j][3] *= a1;
        }

        // ---- O += P V (3-pass) ----
        #pragma unroll
        for (int j = 0; j < 8; j++) {
            #pragma unroll
            for (int cc = 0; cc < 4; cc++) {
                int kk = cc * 16 + 2 * tig;
                uint32_t vbh[2], vbl2[2];
                vbh[0]  = *(const uint32_t*)&sVh[(j * 8 + grp) * KPITCH + kk];
                vbh[1]  = *(const uint32_t*)&sVh[(j * 8 + grp) * KPITCH + kk + 8];
                vbl2[0] = *(const uint32_t*)&sVl[(j * 8 + grp) * KPITCH + kk];
                vbl2[1] = *(const uint32_t*)&sVl[(j * 8 + grp) * KPITCH + kk + 8];
                mma16816(o[j], pfh[cc], vbh);
                mma16816(o[j], pfh[cc], vbl2);
                mma16816(o[j], pfl[cc], vbh);
            }
        }
        __syncthreads();
    }

    // ---- epilogue ----
    const int b = bh >> 4;
    const int h = bh & 15;
    float inv0 = 1.0f / l0, inv1 = 1.0f / l1;
    int s0 = q0 + wid * 16 + grp;
    int s1 = s0 + 8;
    #pragma unroll
    for (int j = 0; j < 8; j++) {
        int col = h * HD + j * 8 + 2 * tig;
        __nv_bfloat162 lo2;
        __nv_bfloat162 hi2 = split_pack(o[j][0] * inv0, o[j][1] * inv0, &lo2);
        size_t off0 = ((size_t)b * SEQ + s0) * HIDDEN + col;
        *(__nv_bfloat162*)(Ohi + off0) = hi2;
        *(__nv_bfloat162*)(Olo + off0) = lo2;
        hi2 = split_pack(o[j][2] * inv1, o[j][3] * inv1, &lo2);
        size_t off1 = ((size_t)b * SEQ + s1) * HIDDEN + col;
        *(__nv_bfloat162*)(Ohi + off1) = hi2;
        *(__nv_bfloat162*)(Olo + off1) = lo2;
    }
}

// ---------------------------------------------------------------------------
extern "C" void kernel_launch(void* const* d_in, const int* in_sizes, int n_in,
                              void* d_out, int out_size)
{
    const float* x     = (const float*)d_in[0];
    const float* W_qkv = (const float*)d_in[1];
    const float* b_qkv = (const float*)d_in[2];
    const float* W_out = (const float*)d_in[3];
    const float* b_out = (const float*)d_in[4];
    float* out = (float*)d_out;

    static __nv_bfloat16 *pah = nullptr, *pal, *pwqh, *pwql, *pwoh, *pwol;
    static __nv_bfloat16 *pqh, *pql, *pkh, *pkl, *pvth, *pvtl;
    if (!pah) {
        cudaGetSymbolAddress((void**)&pah, g_a_hi);
        cudaGetSymbolAddress((void**)&pal, g_a_lo);
        cudaGetSymbolAddress((void**)&pwqh, g_wq_hi);
        cudaGetSymbolAddress((void**)&pwql, g_wq_lo);
        cudaGetSymbolAddress((void**)&pwoh, g_wo_hi);
        cudaGetSymbolAddress((void**)&pwol, g_wo_lo);
        cudaGetSymbolAddress((void**)&pqh, g_qh);
        cudaGetSymbolAddress((void**)&pql, g_ql);
        cudaGetSymbolAddress((void**)&pkh, g_kh);
        cudaGetSymbolAddress((void**)&pkl, g_kl);
        cudaGetSymbolAddress((void**)&pvth, g_vth);
        cudaGetSymbolAddress((void**)&pvtl, g_vtl);
        cudaFuncSetAttribute(hmma_gemm, cudaFuncAttributeMaxDynamicSharedMemorySize, GEMM_SMEM);
        cudaFuncSetAttribute(attn_hmma, cudaFuncAttributeMaxDynamicSharedMemorySize, ATTN_SMEM);
    }

    const int n4 = MTOT * HIDDEN / 4;

    split_kernel<<<n4 / 256, 256>>>(x, pah, pal, n4);
    {
        dim3 g(3 * HIDDEN / 32, HIDDEN / 32);
        tsplit_kernel<<<g, dim3(32, 8)>>>(W_qkv, pwqh, pwql, HIDDEN, 3 * HIDDEN);
    }
    {
        dim3 g(HIDDEN / 32, HIDDEN / 32);
        tsplit_kernel<<<g, dim3(32, 8)>>>(W_out, pwoh, pwol, HIDDEN, HIDDEN);
    }

    {
        dim3 g(3 * HIDDEN / 128, MTOT / 128);
        hmma_gemm<<<g, 256, GEMM_SMEM>>>(pah, pal, pwqh, pwql, b_qkv, nullptr,
                                         pqh, pql, pkh, pkl, pvth, pvtl,
                                         MTOT, 3 * HIDDEN, HIDDEN, 1);
    }

    {
        dim3 g(SEQ / 128, BATCH * HEADS);
        attn_hmma<<<g, 256, ATTN_SMEM>>>(pqh, pql, pkh, pkl, pvth, pvtl, pah, pal);
    }

    {
        dim3 g(HIDDEN / 128, MTOT / 128);
        hmma_gemm<<<g, 256, GEMM_SMEM>>>(pah, pal, pwoh, pwol, b_out, out,
                                         nullptr, nullptr, nullptr, nullptr, nullptr, nullptr,
                                         MTOT, HIDDEN, HIDDEN, 0);
    }
}

// round 7
// speedup vs baseline: 2.6872x; 1.0012x over previous
#include <cuda_runtime.h>
#include <cuda_bf16.h>
#include <math.h>
#include <stdint.h>

#define HIDDEN 1024
#define HEADS  16
#define HD     64
#define BATCH  4
#define SEQ    2048
#define MTOT   (BATCH * SEQ)   // 8192

// ---------------- scratch (device globals; no allocs allowed) --------------
__device__ __nv_bfloat16 g_a_hi[MTOT * HIDDEN];
__device__ __nv_bfloat16 g_a_lo[MTOT * HIDDEN];
__device__ __nv_bfloat16 g_wq_hi[3 * HIDDEN * HIDDEN];
__device__ __nv_bfloat16 g_wq_lo[3 * HIDDEN * HIDDEN];
__device__ __nv_bfloat16 g_wo_hi[HIDDEN * HIDDEN];
__device__ __nv_bfloat16 g_wo_lo[HIDDEN * HIDDEN];
__device__ __nv_bfloat16 g_qh[BATCH * HEADS * SEQ * HD];
__device__ __nv_bfloat16 g_ql[BATCH * HEADS * SEQ * HD];
__device__ __nv_bfloat16 g_kh[BATCH * HEADS * SEQ * HD];
__device__ __nv_bfloat16 g_kl[BATCH * HEADS * SEQ * HD];
__device__ __nv_bfloat16 g_vth[BATCH * HEADS * HD * SEQ];
__device__ __nv_bfloat16 g_vtl[BATCH * HEADS * HD * SEQ];

// ---------------- cp.async helpers -----------------------------------------
__device__ __forceinline__ void cp_async16(uint32_t saddr, const void* gptr) {
    asm volatile("cp.async.ca.shared.global [%0], [%1], 16;"
                 :: "r"(saddr), "l"(gptr));
}
#define CP_COMMIT()  asm volatile("cp.async.commit_group;" ::: "memory")
#define CP_WAIT(n)   asm volatile("cp.async.wait_group %0;" :: "n"(n) : "memory")

// ---------------------------------------------------------------------------
__global__ __launch_bounds__(256) void split_kernel(
    const float* __restrict__ src, __nv_bfloat16* __restrict__ hi,
    __nv_bfloat16* __restrict__ lo, int n4)
{
    int i = blockIdx.x * blockDim.x + threadIdx.x;
    if (i >= n4) return;
    float4 v = ((const float4*)src)[i];
    float xs[4] = {v.x, v.y, v.z, v.w};
    __nv_bfloat16 h[4], l[4];
    #pragma unroll
    for (int j = 0; j < 4; j++) {
        h[j] = __float2bfloat16_rn(xs[j]);
        l[j] = __float2bfloat16_rn(xs[j] - __bfloat162float(h[j]));
    }
    ((__nv_bfloat162*)hi)[2 * i]     = __nv_bfloat162(h[0], h[1]);
    ((__nv_bfloat162*)hi)[2 * i + 1] = __nv_bfloat162(h[2], h[3]);
    ((__nv_bfloat162*)lo)[2 * i]     = __nv_bfloat162(l[0], l[1]);
    ((__nv_bfloat162*)lo)[2 * i + 1] = __nv_bfloat162(l[2], l[3]);
}

__global__ void tsplit_kernel(const float* __restrict__ W,
                              __nv_bfloat16* __restrict__ hi,
                              __nv_bfloat16* __restrict__ lo, int K, int N)
{
    __shared__ float t[32][33];
    int n0 = blockIdx.x * 32, k0 = blockIdx.y * 32;
    for (int r = threadIdx.y; r < 32; r += 8)
        t[r][threadIdx.x] = W[(size_t)(k0 + r) * N + n0 + threadIdx.x];
    __syncthreads();
    for (int r = threadIdx.y; r < 32; r += 8) {
        float x = t[threadIdx.x][r];
        __nv_bfloat16 h = __float2bfloat16_rn(x);
        __nv_bfloat16 l = __float2bfloat16_rn(x - __bfloat162float(h));
        size_t o = (size_t)(n0 + r) * K + k0 + threadIdx.x;
        hi[o] = h;
        lo[o] = l;
    }
}

// ---------------------------------------------------------------------------
__device__ __forceinline__ void mma16816(float* c, const uint32_t* a, const uint32_t* b)
{
    asm volatile(
        "mma.sync.aligned.m16n8k16.row.col.f32.bf16.bf16.f32 "
        "{%0,%1,%2,%3}, {%4,%5,%6,%7}, {%8,%9}, {%0,%1,%2,%3};"
        : "+f"(c[0]), "+f"(c[1]), "+f"(c[2]), "+f"(c[3])
        : "r"(a[0]), "r"(a[1]), "r"(a[2]), "r"(a[3]), "r"(b[0]), "r"(b[1]));
}

__device__ __forceinline__ __nv_bfloat162 split_pack(float x, float y,
                                                     __nv_bfloat162* lo)
{
    __nv_bfloat16 hx = __float2bfloat16_rn(x);
    __nv_bfloat16 hy = __float2bfloat16_rn(y);
    *lo = __nv_bfloat162(__float2bfloat16_rn(x - __bfloat162float(hx)),
                         __float2bfloat16_rn(y - __bfloat162float(hy)));
    return __nv_bfloat162(hx, hy);
}

// ---------------------------------------------------------------------------
// HMMA GEMM, cp.async 2-stage pipeline, 2 CTAs/SM.
// ---------------------------------------------------------------------------
#define SPAD 40
#define GST  40960
#define GEMM_SMEM (2 * GST)

__global__ __launch_bounds__(256, 2) void hmma_gemm(
    const __nv_bfloat16* __restrict__ Ahi, const __nv_bfloat16* __restrict__ Alo,
    const __nv_bfloat16* __restrict__ Bhi, const __nv_bfloat16* __restrict__ Blo,
    const float* __restrict__ bias, float* __restrict__ C,
    __nv_bfloat16* __restrict__ qh, __nv_bfloat16* __restrict__ ql,
    __nv_bfloat16* __restrict__ kh, __nv_bfloat16* __restrict__ kl,
    __nv_bfloat16* __restrict__ vth, __nv_bfloat16* __restrict__ vtl,
    int M, int N, int K, int mode)
{
    extern __shared__ char smem[];
    const uint32_t sbase = (uint32_t)__cvta_generic_to_shared(smem);

    const int tid  = threadIdx.x;
    const int wid  = tid >> 5;
    const int lane = tid & 31;
    const int grp  = lane >> 2;
    const int tig  = lane & 3;
    const int wm   = wid & 1;
    const int wn   = wid >> 1;
    const int bm   = blockIdx.y * 128;
    const int bn   = blockIdx.x * 128;
    const int NT   = K / 32;

    const int r0 = tid >> 2,          ch0 = tid & 3;
    const int r1 = (tid + 256) >> 2,  ch1 = (tid + 256) & 3;

    float c[4][4][4];
    #pragma unroll
    for (int i = 0; i < 4; i++)
        #pragma unroll
        for (int j = 0; j < 4; j++)
            #pragma unroll
            for (int p = 0; p < 4; p++) c[i][j][p] = 0.f;

    auto issue_tile = [&](int kt, int stage) {
        const int k0 = kt * 32;
        const uint32_t st = sbase + stage * GST;
        {
            uint32_t so = (uint32_t)(r0 * SPAD + ch0 * 8) * 2;
            size_t ga = (size_t)(bm + r0) * K + k0 + ch0 * 8;
            size_t gb = (size_t)(bn + r0) * K + k0 + ch0 * 8;
            cp_async16(st + so,         Ahi + ga);
            cp_async16(st + 10240 + so, Alo + ga);
            cp_async16(st + 20480 + so, Bhi + gb);
            cp_async16(st + 30720 + so, Blo + gb);
        }
        {
            uint32_t so = (uint32_t)(r1 * SPAD + ch1 * 8) * 2;
            size_t ga = (size_t)(bm + r1) * K + k0 + ch1 * 8;
            size_t gb = (size_t)(bn + r1) * K + k0 + ch1 * 8;
            cp_async16(st + so,         Ahi + ga);
            cp_async16(st + 10240 + so, Alo + ga);
            cp_async16(st + 20480 + so, Bhi + gb);
            cp_async16(st + 30720 + so, Blo + gb);
        }
        CP_COMMIT();
    };

    issue_tile(0, 0);

    for (int kt = 0; kt < NT; kt++) {
        if (kt + 1 < NT) {
            issue_tile(kt + 1, (kt + 1) & 1);
            CP_WAIT(1);
        } else {
            CP_WAIT(0);
        }
        __syncthreads();

        const char* stp = smem + (kt & 1) * GST;
        const __nv_bfloat16* sAh = (const __nv_bfloat16*)(stp);
        const __nv_bfloat16* sAl = (const __nv_bfloat16*)(stp + 10240);
        const __nv_bfloat16* sBh = (const __nv_bfloat16*)(stp + 20480);
        const __nv_bfloat16* sBl = (const __nv_bfloat16*)(stp + 30720);

        #pragma unroll
        for (int ks = 0; ks < 2; ks++) {
            const int kk = ks * 16 + tig * 2;
            uint32_t ah[4][4], bh[4][2];
            #pragma unroll
            for (int i = 0; i < 4; i++) {
                int ar = wm * 64 + i * 16 + grp;
                ah[i][0] = *(const uint32_t*)&sAh[ar * SPAD + kk];
                ah[i][1] = *(const uint32_t*)&sAh[(ar + 8) * SPAD + kk];
                ah[i][2] = *(const uint32_t*)&sAh[ar * SPAD + kk + 8];
                ah[i][3] = *(const uint32_t*)&sAh[(ar + 8) * SPAD + kk + 8];
            }
            #pragma unroll
            for (int j = 0; j < 4; j++) {
                int br = wn * 32 + j * 8 + grp;
                bh[j][0] = *(const uint32_t*)&sBh[br * SPAD + kk];
                bh[j][1] = *(const uint32_t*)&sBh[br * SPAD + kk + 8];
            }
            #pragma unroll
            for (int i = 0; i < 4; i++)
                #pragma unroll
                for (int j = 0; j < 4; j++) mma16816(c[i][j], ah[i], bh[j]);
            uint32_t bl[4][2];
            #pragma unroll
            for (int j = 0; j < 4; j++) {
                int br = wn * 32 + j * 8 + grp;
                bl[j][0] = *(const uint32_t*)&sBl[br * SPAD + kk];
                bl[j][1] = *(const uint32_t*)&sBl[br * SPAD + kk + 8];
            }
            #pragma unroll
            for (int i = 0; i < 4; i++)
                #pragma unroll
                for (int j = 0; j < 4; j++) mma16816(c[i][j], ah[i], bl[j]);
            uint32_t al[4][4];
            #pragma unroll
            for (int i = 0; i < 4; i++) {
                int ar = wm * 64 + i * 16 + grp;
                al[i][0] = *(const uint32_t*)&sAl[ar * SPAD + kk];
                al[i][1] = *(const uint32_t*)&sAl[(ar + 8) * SPAD + kk];
                al[i][2] = *(const uint32_t*)&sAl[ar * SPAD + kk + 8];
                al[i][3] = *(const uint32_t*)&sAl[(ar + 8) * SPAD + kk + 8];
            }
            #pragma unroll
            for (int i = 0; i < 4; i++)
                #pragma unroll
                for (int j = 0; j < 4; j++) mma16816(c[i][j], al[i], bh[j]);
        }
        __syncthreads();
    }

    #pragma unroll
    for (int i = 0; i < 4; i++) {
        #pragma unroll
        for (int j = 0; j < 4; j++) {
            int n0 = bn + wn * 32 + j * 8 + tig * 2;
            float2 bv = *(const float2*)(bias + n0);
            #pragma unroll
            for (int half = 0; half < 2; half++) {
                int m = bm + wm * 64 + i * 16 + grp + half * 8;
                float rx = c[i][j][half * 2 + 0] + bv.x;
                float ry = c[i][j][half * 2 + 1] + bv.y;
                if (mode == 0) {
                    *(float2*)(C + (size_t)m * N + n0) = make_float2(rx, ry);
                } else {
                    int sel = n0 >> 10, rem = n0 & 1023;
                    int h = rem >> 6, hd0 = rem & 63;
                    int b = m >> 11, s = m & 2047;
                    size_t bh_ = (size_t)b * HEADS + h;
                    if (sel == 0) {
                        __nv_bfloat162 lo2;
                        __nv_bfloat162 hi2 = split_pack(rx * 0.125f, ry * 0.125f, &lo2);
                        size_t off = (bh_ * SEQ + s) * HD + hd0;
                        *(__nv_bfloat162*)(qh + off) = hi2;
                        *(__nv_bfloat162*)(ql + off) = lo2;
                    } else if (sel == 1) {
                        __nv_bfloat162 lo2;
                        __nv_bfloat162 hi2 = split_pack(rx, ry, &lo2);
                        size_t off = (bh_ * SEQ + s) * HD + hd0;
                        *(__nv_bfloat162*)(kh + off) = hi2;
                        *(__nv_bfloat162*)(kl + off) = lo2;
                    } else {
                        __nv_bfloat162 lo2;
                        __nv_bfloat162 hi2 = split_pack(rx, ry, &lo2);
                        size_t o0 = (bh_ * HD + hd0) * SEQ + s;
                        size_t o1 = (bh_ * HD + hd0 + 1) * SEQ + s;
                        vth[o0] = hi2.x; vth[o1] = hi2.y;
                        vtl[o0] = lo2.x; vtl[o1] = lo2.y;
                    }
                }
            }
        }
    }
}

// ---------------------------------------------------------------------------
// HMMA flash attention: 128 q-rows per CTA (8 warps, 256 thr), 64-key tiles,
// cp.async 2-stage, 2 CTAs/SM. Each K/V tile now serves 128 q-rows.
// ---------------------------------------------------------------------------
#define KPITCH 72
#define AST    36864
#define ATTN_SMEM (2 * AST)

__global__ __launch_bounds__(256, 2) void attn_hmma(
    const __nv_bfloat16* __restrict__ qh, const __nv_bfloat16* __restrict__ ql,
    const __nv_bfloat16* __restrict__ kh, const __nv_bfloat16* __restrict__ kl,
    const __nv_bfloat16* __restrict__ vth, const __nv_bfloat16* __restrict__ vtl,
    __nv_bfloat16* __restrict__ Ohi, __nv_bfloat16* __restrict__ Olo)
{
    extern __shared__ char smem[];
    const uint32_t sbase = (uint32_t)__cvta_generic_to_shared(smem);

    const int tid  = threadIdx.x;
    const int wid  = tid >> 5;          // 0..7, each owns 16 q-rows
    const int lane = tid & 31;
    const int grp  = lane >> 2;
    const int tig  = lane & 3;
    const int bh   = blockIdx.y;
    const int q0   = blockIdx.x * 128;

    const __nv_bfloat16* Kbh = kh + (size_t)bh * SEQ * HD;
    const __nv_bfloat16* Kbl = kl + (size_t)bh * SEQ * HD;
    const __nv_bfloat16* Vbh = vth + (size_t)bh * HD * SEQ;
    const __nv_bfloat16* Vbl = vtl + (size_t)bh * HD * SEQ;

    auto issue_tile = [&](int kt, int stage) {
        const uint32_t st = sbase + stage * AST;
        #pragma unroll
        for (int i = 0; i < 2; i++) {
            int g = tid + i * 256;          // 0..511
            int r = g >> 3, ch = g & 7;
            uint32_t so = (uint32_t)(r * KPITCH + ch * 8) * 2;
            cp_async16(st + so,         Kbh + (size_t)(kt * 64 + r) * HD + ch * 8);
            cp_async16(st + 9216 + so,  Kbl + (size_t)(kt * 64 + r) * HD + ch * 8);
            cp_async16(st + 18432 + so, Vbh + (size_t)r * SEQ + kt * 64 + ch * 8);
            cp_async16(st + 27648 + so, Vbl + (size_t)r * SEQ + kt * 64 + ch * 8);
        }
        CP_COMMIT();
    };

    issue_tile(0, 0);

    uint32_t qfh[4][4], qfl[4][4];
    {
        const __nv_bfloat16* Qh = qh + ((size_t)bh * SEQ + q0 + wid * 16) * HD;
        const __nv_bfloat16* Ql = ql + ((size_t)bh * SEQ + q0 + wid * 16) * HD;
        #pragma unroll
        for (int cc = 0; cc < 4; cc++) {
            int k0 = cc * 16 + 2 * tig;
            qfh[cc][0] = *(const uint32_t*)(Qh + grp * HD + k0);
            qfh[cc][1] = *(const uint32_t*)(Qh + (grp + 8) * HD + k0);
            qfh[cc][2] = *(const uint32_t*)(Qh + grp * HD + k0 + 8);
            qfh[cc][3] = *(const uint32_t*)(Qh + (grp + 8) * HD + k0 + 8);
            qfl[cc][0] = *(const uint32_t*)(Ql + grp * HD + k0);
            qfl[cc][1] = *(const uint32_t*)(Ql + (grp + 8) * HD + k0);
            qfl[cc][2] = *(const uint32_t*)(Ql + grp * HD + k0 + 8);
            qfl[cc][3] = *(const uint32_t*)(Ql + (grp + 8) * HD + k0 + 8);
        }
    }

    float o[8][4];
    #pragma unroll
    for (int j = 0; j < 8; j++)
        #pragma unroll
        for (int p = 0; p < 4; p++) o[j][p] = 0.f;
    float m0 = -INFINITY, m1 = -INFINITY, l0 = 0.f, l1 = 0.f;

    const int NT = SEQ / 64;
    for (int kt = 0; kt < NT; kt++) {
        if (kt + 1 < NT) {
            issue_tile(kt + 1, (kt + 1) & 1);
            CP_WAIT(1);
        } else {
            CP_WAIT(0);
        }
        __syncthreads();

        const char* stp = smem + (kt & 1) * AST;
        const __nv_bfloat16* sKh = (const __nv_bfloat16*)(stp);
        const __nv_bfloat16* sKl = (const __nv_bfloat16*)(stp + 9216);
        const __nv_bfloat16* sVh = (const __nv_bfloat16*)(stp + 18432);
        const __nv_bfloat16* sVl = (const __nv_bfloat16*)(stp + 27648);

        // ---- S = Q K^T (3-pass) ----
        float s[8][4];
        #pragma unroll
        for (int j = 0; j < 8; j++)
            #pragma unroll
            for (int p = 0; p < 4; p++) s[j][p] = 0.f;
        #pragma unroll
        for (int j = 0; j < 8; j++) {
            #pragma unroll
            for (int cc = 0; cc < 4; cc++) {
                int kk = cc * 16 + 2 * tig;
                uint32_t kbh[2], kbl2[2];
                kbh[0]  = *(const uint32_t*)&sKh[(j * 8 + grp) * KPITCH + kk];
                kbh[1]  = *(const uint32_t*)&sKh[(j * 8 + grp) * KPITCH + kk + 8];
                kbl2[0] = *(const uint32_t*)&sKl[(j * 8 + grp) * KPITCH + kk];
                kbl2[1] = *(const uint32_t*)&sKl[(j * 8 + grp) * KPITCH + kk + 8];
                mma16816(s[j], qfh[cc], kbh);
                mma16816(s[j], qfh[cc], kbl2);
                mma16816(s[j], qfl[cc], kbh);
            }
        }

        // ---- online softmax ----
        float mx0 = -INFINITY, mx1 = -INFINITY;
        #pragma unroll
        for (int j = 0; j < 8; j++) {
            mx0 = fmaxf(mx0, fmaxf(s[j][0], s[j][1]));
            mx1 = fmaxf(mx1, fmaxf(s[j][2], s[j][3]));
        }
        mx0 = fmaxf(mx0, __shfl_xor_sync(0xffffffffu, mx0, 1));
        mx0 = fmaxf(mx0, __shfl_xor_sync(0xffffffffu, mx0, 2));
        mx1 = fmaxf(mx1, __shfl_xor_sync(0xffffffffu, mx1, 1));
        mx1 = fmaxf(mx1, __shfl_xor_sync(0xffffffffu, mx1, 2));
        float mn0 = fmaxf(m0, mx0), mn1 = fmaxf(m1, mx1);
        float a0 = __expf(m0 - mn0), a1 = __expf(m1 - mn1);
        m0 = mn0; m1 = mn1;

        uint32_t pfh[4][4], pfl[4][4];
        float ps0 = 0.f, ps1 = 0.f;
        #pragma unroll
        for (int j = 0; j < 8; j++) {
            float p0 = __expf(s[j][0] - m0);
            float p1 = __expf(s[j][1] - m0);
            float p2 = __expf(s[j][2] - m1);
            float p3 = __expf(s[j][3] - m1);
            ps0 += p0 + p1;
            ps1 += p2 + p3;
            int cc = j >> 1, half = j & 1;
            __nv_bfloat162 lo2a, lo2b;
            __nv_bfloat162 hi2a = split_pack(p0, p1, &lo2a);
            __nv_bfloat162 hi2b = split_pack(p2, p3, &lo2b);
            pfh[cc][0 + 2 * half] = *(uint32_t*)&hi2a;
            pfh[cc][1 + 2 * half] = *(uint32_t*)&hi2b;
            pfl[cc][0 + 2 * half] = *(uint32_t*)&lo2a;
            pfl[cc][1 + 2 * half] = *(uint32_t*)&lo2b;
        }
        ps0 += __shfl_xor_sync(0xffffffffu, ps0, 1);
        ps0 += __shfl_xor_sync(0xffffffffu, ps0, 2);
        ps1 += __shfl_xor_sync(0xffffffffu, ps1, 1);
        ps1 += __shfl_xor_sync(0xffffffffu, ps1, 2);
        l0 = l0 * a0 + ps0;
        l1 = l1 * a1 + ps1;

        #pragma unroll
        for (int j = 0; j < 8; j++) {
            o[j][0] *= a0; o[j][1] *= a0;
            o[j][2] *= a1; o[j][3] *= a1;
        }

        // ---- O += P V (3-pass) ----
        #pragma unroll
        for (int j = 0; j < 8; j++) {
            #pragma unroll
            for (int cc = 0; cc < 4; cc++) {
                int kk = cc * 16 + 2 * tig;
                uint32_t vbh[2], vbl2[2];
                vbh[0]  = *(const uint32_t*)&sVh[(j * 8 + grp) * KPITCH + kk];
                vbh[1]  = *(const uint32_t*)&sVh[(j * 8 + grp) * KPITCH + kk + 8];
                vbl2[0] = *(const uint32_t*)&sVl[(j * 8 + grp) * KPITCH + kk];
                vbl2[1] = *(const uint32_t*)&sVl[(j * 8 + grp) * KPITCH + kk + 8];
                mma16816(o[j], pfh[cc], vbh);
                mma16816(o[j], pfh[cc], vbl2);
                mma16816(o[j], pfl[cc], vbh);
            }
        }
        __syncthreads();
    }

    // ---- epilogue ----
    const int b = bh >> 4;
    const int h = bh & 15;
    float inv0 = 1.0f / l0, inv1 = 1.0f / l1;
    int s0 = q0 + wid * 16 + grp;
    int s1 = s0 + 8;
    #pragma unroll
    for (int j = 0; j < 8; j++) {
        int col = h * HD + j * 8 + 2 * tig;
        __nv_bfloat162 lo2;
        __nv_bfloat162 hi2 = split_pack(o[j][0] * inv0, o[j][1] * inv0, &lo2);
        size_t off0 = ((size_t)b * SEQ + s0) * HIDDEN + col;
        *(__nv_bfloat162*)(Ohi + off0) = hi2;
        *(__nv_bfloat162*)(Olo + off0) = lo2;
        hi2 = split_pack(o[j][2] * inv1, o[j][3] * inv1, &lo2);
        size_t off1 = ((size_t)b * SEQ + s1) * HIDDEN + col;
        *(__nv_bfloat162*)(Ohi + off1) = hi2;
        *(__nv_bfloat162*)(Olo + off1) = lo2;
    }
}

// ---------------------------------------------------------------------------
extern "C" void kernel_launch(void* const* d_in, const int* in_sizes, int n_in,
                              void* d_out, int out_size)
{
    const float* x     = (const float*)d_in[0];
    const float* W_qkv = (const float*)d_in[1];
    const float* b_qkv = (const float*)d_in[2];
    const float* W_out = (const float*)d_in[3];
    const float* b_out = (const float*)d_in[4];
    float* out = (float*)d_out;

    static __nv_bfloat16 *pah = nullptr, *pal, *pwqh, *pwql, *pwoh, *pwol;
    static __nv_bfloat16 *pqh, *pql, *pkh, *pkl, *pvth, *pvtl;
    if (!pah) {
        cudaGetSymbolAddress((void**)&pah, g_a_hi);
        cudaGetSymbolAddress((void**)&pal, g_a_lo);
        cudaGetSymbolAddress((void**)&pwqh, g_wq_hi);
        cudaGetSymbolAddress((void**)&pwql, g_wq_lo);
        cudaGetSymbolAddress((void**)&pwoh, g_wo_hi);
        cudaGetSymbolAddress((void**)&pwol, g_wo_lo);
        cudaGetSymbolAddress((void**)&pqh, g_qh);
        cudaGetSymbolAddress((void**)&pql, g_ql);
        cudaGetSymbolAddress((void**)&pkh, g_kh);
        cudaGetSymbolAddress((void**)&pkl, g_kl);
        cudaGetSymbolAddress((void**)&pvth, g_vth);
        cudaGetSymbolAddress((void**)&pvtl, g_vtl);
        cudaFuncSetAttribute(hmma_gemm, cudaFuncAttributeMaxDynamicSharedMemorySize, GEMM_SMEM);
        cudaFuncSetAttribute(attn_hmma, cudaFuncAttributeMaxDynamicSharedMemorySize, ATTN_SMEM);
    }

    const int n4 = MTOT * HIDDEN / 4;

    split_kernel<<<n4 / 256, 256>>>(x, pah, pal, n4);
    {
        dim3 g(3 * HIDDEN / 32, HIDDEN / 32);
        tsplit_kernel<<<g, dim3(32, 8)>>>(W_qkv, pwqh, pwql, HIDDEN, 3 * HIDDEN);
    }
    {
        dim3 g(HIDDEN / 32, HIDDEN / 32);
        tsplit_kernel<<<g, dim3(32, 8)>>>(W_out, pwoh, pwol, HIDDEN, HIDDEN);
    }

    {
        dim3 g(3 * HIDDEN / 128, MTOT / 128);
        hmma_gemm<<<g, 256, GEMM_SMEM>>>(pah, pal, pwqh, pwql, b_qkv, nullptr,
                                         pqh, pql, pkh, pkl, pvth, pvtl,
                                         MTOT, 3 * HIDDEN, HIDDEN, 1);
    }

    {
        dim3 g(SEQ / 128, BATCH * HEADS);
        attn_hmma<<<g, 256, ATTN_SMEM>>>(pqh, pql, pkh, pkl, pvth, pvtl, pah, pal);
    }

    {
        dim3 g(HIDDEN / 128, MTOT / 128);
        hmma_gemm<<<g, 256, GEMM_SMEM>>>(pah, pal, pwoh, pwol, b_out, out,
                                         nullptr, nullptr, nullptr, nullptr, nullptr, nullptr,
                                         MTOT, HIDDEN, HIDDEN, 0);
    }
}

// round 8
// speedup vs baseline: 3.0014x; 1.1169x over previous
#include <cuda_runtime.h>
#include <cuda_bf16.h>
#include <math.h>
#include <stdint.h>

#define HIDDEN 1024
#define HEADS  16
#define HD     64
#define BATCH  4
#define SEQ    2048
#define MTOT   (BATCH * SEQ)   // 8192

// ---------------- scratch (device globals; no allocs allowed) --------------
__device__ __nv_bfloat16 g_a_hi[MTOT * HIDDEN];
__device__ __nv_bfloat16 g_a_lo[MTOT * HIDDEN];
__device__ __nv_bfloat16 g_wq_hi[3 * HIDDEN * HIDDEN];
__device__ __nv_bfloat16 g_wq_lo[3 * HIDDEN * HIDDEN];
__device__ __nv_bfloat16 g_wo_hi[HIDDEN * HIDDEN];
__device__ __nv_bfloat16 g_wo_lo[HIDDEN * HIDDEN];
__device__ __nv_bfloat16 g_qh[BATCH * HEADS * SEQ * HD];
__device__ __nv_bfloat16 g_ql[BATCH * HEADS * SEQ * HD];
__device__ __nv_bfloat16 g_kh[BATCH * HEADS * SEQ * HD];
__device__ __nv_bfloat16 g_kl[BATCH * HEADS * SEQ * HD];
__device__ __nv_bfloat16 g_vth[BATCH * HEADS * HD * SEQ];
__device__ __nv_bfloat16 g_vtl[BATCH * HEADS * HD * SEQ];

// ---------------- async-copy / ldmatrix helpers -----------------------------
__device__ __forceinline__ void cp_async16(uint32_t saddr, const void* gptr) {
    asm volatile("cp.async.ca.shared.global [%0], [%1], 16;"
                 :: "r"(saddr), "l"(gptr));
}
#define CP_COMMIT()  asm volatile("cp.async.commit_group;" ::: "memory")
#define CP_WAIT(n)   asm volatile("cp.async.wait_group %0;" :: "n"(n) : "memory")

__device__ __forceinline__ void ldsm4(uint32_t* r, uint32_t addr) {
    asm volatile("ldmatrix.sync.aligned.m8n8.x4.shared.b16 {%0,%1,%2,%3}, [%4];"
                 : "=r"(r[0]), "=r"(r[1]), "=r"(r[2]), "=r"(r[3]) : "r"(addr));
}

// ---------------------------------------------------------------------------
__global__ __launch_bounds__(256) void split_kernel(
    const float* __restrict__ src, __nv_bfloat16* __restrict__ hi,
    __nv_bfloat16* __restrict__ lo, int n4)
{
    int i = blockIdx.x * blockDim.x + threadIdx.x;
    if (i >= n4) return;
    float4 v = ((const float4*)src)[i];
    float xs[4] = {v.x, v.y, v.z, v.w};
    __nv_bfloat16 h[4], l[4];
    #pragma unroll
    for (int j = 0; j < 4; j++) {
        h[j] = __float2bfloat16_rn(xs[j]);
        l[j] = __float2bfloat16_rn(xs[j] - __bfloat162float(h[j]));
    }
    ((__nv_bfloat162*)hi)[2 * i]     = __nv_bfloat162(h[0], h[1]);
    ((__nv_bfloat162*)hi)[2 * i + 1] = __nv_bfloat162(h[2], h[3]);
    ((__nv_bfloat162*)lo)[2 * i]     = __nv_bfloat162(l[0], l[1]);
    ((__nv_bfloat162*)lo)[2 * i + 1] = __nv_bfloat162(l[2], l[3]);
}

__global__ void tsplit_kernel(const float* __restrict__ W,
                              __nv_bfloat16* __restrict__ hi,
                              __nv_bfloat16* __restrict__ lo, int K, int N)
{
    __shared__ float t[32][33];
    int n0 = blockIdx.x * 32, k0 = blockIdx.y * 32;
    for (int r = threadIdx.y; r < 32; r += 8)
        t[r][threadIdx.x] = W[(size_t)(k0 + r) * N + n0 + threadIdx.x];
    __syncthreads();
    for (int r = threadIdx.y; r < 32; r += 8) {
        float x = t[threadIdx.x][r];
        __nv_bfloat16 h = __float2bfloat16_rn(x);
        __nv_bfloat16 l = __float2bfloat16_rn(x - __bfloat162float(h));
        size_t o = (size_t)(n0 + r) * K + k0 + threadIdx.x;
        hi[o] = h;
        lo[o] = l;
    }
}

// ---------------------------------------------------------------------------
__device__ __forceinline__ void mma16816(float* c, const uint32_t* a, const uint32_t* b)
{
    asm volatile(
        "mma.sync.aligned.m16n8k16.row.col.f32.bf16.bf16.f32 "
        "{%0,%1,%2,%3}, {%4,%5,%6,%7}, {%8,%9}, {%0,%1,%2,%3};"
        : "+f"(c[0]), "+f"(c[1]), "+f"(c[2]), "+f"(c[3])
        : "r"(a[0]), "r"(a[1]), "r"(a[2]), "r"(a[3]), "r"(b[0]), "r"(b[1]));
}

__device__ __forceinline__ __nv_bfloat162 split_pack(float x, float y,
                                                     __nv_bfloat162* lo)
{
    __nv_bfloat16 hx = __float2bfloat16_rn(x);
    __nv_bfloat16 hy = __float2bfloat16_rn(y);
    *lo = __nv_bfloat162(__float2bfloat16_rn(x - __bfloat162float(hx)),
                         __float2bfloat16_rn(y - __bfloat162float(hy)));
    return __nv_bfloat162(hx, hy);
}

// ---------------------------------------------------------------------------
// HMMA GEMM, cp.async 2-stage pipeline + ldmatrix fragment loads, 2 CTAs/SM.
// ---------------------------------------------------------------------------
#define SPAD 40
#define GST  40960
#define GEMM_SMEM (2 * GST)

__global__ __launch_bounds__(256, 2) void hmma_gemm(
    const __nv_bfloat16* __restrict__ Ahi, const __nv_bfloat16* __restrict__ Alo,
    const __nv_bfloat16* __restrict__ Bhi, const __nv_bfloat16* __restrict__ Blo,
    const float* __restrict__ bias, float* __restrict__ C,
    __nv_bfloat16* __restrict__ qh, __nv_bfloat16* __restrict__ ql,
    __nv_bfloat16* __restrict__ kh, __nv_bfloat16* __restrict__ kl,
    __nv_bfloat16* __restrict__ vth, __nv_bfloat16* __restrict__ vtl,
    int M, int N, int K, int mode)
{
    extern __shared__ char smem[];
    const uint32_t sbase = (uint32_t)__cvta_generic_to_shared(smem);

    const int tid  = threadIdx.x;
    const int wid  = tid >> 5;
    const int lane = tid & 31;
    const int grp  = lane >> 2;
    const int tig  = lane & 3;
    const int wm   = wid & 1;
    const int wn   = wid >> 1;
    const int bm   = blockIdx.y * 128;
    const int bn   = blockIdx.x * 128;
    const int NT   = K / 32;

    // ldmatrix per-lane offsets: mat = which 8x8 matrix this lane's addr feeds
    const int mat = lane >> 3, lr = lane & 7;
    const int a_row = (mat & 1) * 8 + lr;   // within m16 tile
    const int a_col = (mat >> 1) * 8;       // within k16
    const int b_jo  = mat >> 1;             // j within pair
    const int b_col = (mat & 1) * 8;

    const int r0 = tid >> 2,          ch0 = tid & 3;
    const int r1 = (tid + 256) >> 2,  ch1 = (tid + 256) & 3;

    float c[4][4][4];
    #pragma unroll
    for (int i = 0; i < 4; i++)
        #pragma unroll
        for (int j = 0; j < 4; j++)
            #pragma unroll
            for (int p = 0; p < 4; p++) c[i][j][p] = 0.f;

    auto issue_tile = [&](int kt, int stage) {
        const int k0 = kt * 32;
        const uint32_t st = sbase + stage * GST;
        {
            uint32_t so = (uint32_t)(r0 * SPAD + ch0 * 8) * 2;
            size_t ga = (size_t)(bm + r0) * K + k0 + ch0 * 8;
            size_t gb = (size_t)(bn + r0) * K + k0 + ch0 * 8;
            cp_async16(st + so,         Ahi + ga);
            cp_async16(st + 10240 + so, Alo + ga);
            cp_async16(st + 20480 + so, Bhi + gb);
            cp_async16(st + 30720 + so, Blo + gb);
        }
        {
            uint32_t so = (uint32_t)(r1 * SPAD + ch1 * 8) * 2;
            size_t ga = (size_t)(bm + r1) * K + k0 + ch1 * 8;
            size_t gb = (size_t)(bn + r1) * K + k0 + ch1 * 8;
            cp_async16(st + so,         Ahi + ga);
            cp_async16(st + 10240 + so, Alo + ga);
            cp_async16(st + 20480 + so, Bhi + gb);
            cp_async16(st + 30720 + so, Blo + gb);
        }
        CP_COMMIT();
    };

    issue_tile(0, 0);

    for (int kt = 0; kt < NT; kt++) {
        if (kt + 1 < NT) {
            issue_tile(kt + 1, (kt + 1) & 1);
            CP_WAIT(1);
        } else {
            CP_WAIT(0);
        }
        __syncthreads();

        const uint32_t st = sbase + (kt & 1) * GST;

        #pragma unroll
        for (int ks = 0; ks < 2; ks++) {
            const int kk = ks * 16;
            uint32_t ah[4][4], al[4][4], bh[2][4], bl[2][4];
            #pragma unroll
            for (int i = 0; i < 4; i++) {
                uint32_t ad = st + (uint32_t)((wm * 64 + i * 16 + a_row) * SPAD + kk + a_col) * 2;
                ldsm4(ah[i], ad);
                ldsm4(al[i], ad + 10240);
            }
            #pragma unroll
            for (int p = 0; p < 2; p++) {
                uint32_t bd = st + 20480 +
                    (uint32_t)((wn * 32 + (p * 2 + b_jo) * 8 + lr) * SPAD + kk + b_col) * 2;
                ldsm4(bh[p], bd);
                ldsm4(bl[p], bd + 10240);
            }
            // pass 1: Ahi * Bhi
            #pragma unroll
            for (int i = 0; i < 4; i++)
                #pragma unroll
                for (int j = 0; j < 4; j++)
                    mma16816(c[i][j], ah[i], &bh[j >> 1][(j & 1) * 2]);
            // pass 2: Ahi * Blo
            #pragma unroll
            for (int i = 0; i < 4; i++)
                #pragma unroll
                for (int j = 0; j < 4; j++)
                    mma16816(c[i][j], ah[i], &bl[j >> 1][(j & 1) * 2]);
            // pass 3: Alo * Bhi
            #pragma unroll
            for (int i = 0; i < 4; i++)
                #pragma unroll
                for (int j = 0; j < 4; j++)
                    mma16816(c[i][j], al[i], &bh[j >> 1][(j & 1) * 2]);
        }
        __syncthreads();
    }

    #pragma unroll
    for (int i = 0; i < 4; i++) {
        #pragma unroll
        for (int j = 0; j < 4; j++) {
            int n0 = bn + wn * 32 + j * 8 + tig * 2;
            float2 bv = *(const float2*)(bias + n0);
            #pragma unroll
            for (int half = 0; half < 2; half++) {
                int m = bm + wm * 64 + i * 16 + grp + half * 8;
                float rx = c[i][j][half * 2 + 0] + bv.x;
                float ry = c[i][j][half * 2 + 1] + bv.y;
                if (mode == 0) {
                    *(float2*)(C + (size_t)m * N + n0) = make_float2(rx, ry);
                } else {
                    int sel = n0 >> 10, rem = n0 & 1023;
                    int h = rem >> 6, hd0 = rem & 63;
                    int b = m >> 11, s = m & 2047;
                    size_t bh_ = (size_t)b * HEADS + h;
                    if (sel == 0) {
                        __nv_bfloat162 lo2;
                        __nv_bfloat162 hi2 = split_pack(rx * 0.125f, ry * 0.125f, &lo2);
                        size_t off = (bh_ * SEQ + s) * HD + hd0;
                        *(__nv_bfloat162*)(qh + off) = hi2;
                        *(__nv_bfloat162*)(ql + off) = lo2;
                    } else if (sel == 1) {
                        __nv_bfloat162 lo2;
                        __nv_bfloat162 hi2 = split_pack(rx, ry, &lo2);
                        size_t off = (bh_ * SEQ + s) * HD + hd0;
                        *(__nv_bfloat162*)(kh + off) = hi2;
                        *(__nv_bfloat162*)(kl + off) = lo2;
                    } else {
                        __nv_bfloat162 lo2;
                        __nv_bfloat162 hi2 = split_pack(rx, ry, &lo2);
                        size_t o0 = (bh_ * HD + hd0) * SEQ + s;
                        size_t o1 = (bh_ * HD + hd0 + 1) * SEQ + s;
                        vth[o0] = hi2.x; vth[o1] = hi2.y;
                        vtl[o0] = lo2.x; vtl[o1] = lo2.y;
                    }
                }
            }
        }
    }
}

// ---------------------------------------------------------------------------
// HMMA flash attention: 128 q-rows/CTA (8 warps), 64-key tiles, cp.async
// 2-stage + ldmatrix fragment loads, 2 CTAs/SM.
// ---------------------------------------------------------------------------
#define KPITCH 72
#define AST    36864
#define ATTN_SMEM (2 * AST)

__global__ __launch_bounds__(256, 2) void attn_hmma(
    const __nv_bfloat16* __restrict__ qh, const __nv_bfloat16* __restrict__ ql,
    const __nv_bfloat16* __restrict__ kh, const __nv_bfloat16* __restrict__ kl,
    const __nv_bfloat16* __restrict__ vth, const __nv_bfloat16* __restrict__ vtl,
    __nv_bfloat16* __restrict__ Ohi, __nv_bfloat16* __restrict__ Olo)
{
    extern __shared__ char smem[];
    const uint32_t sbase = (uint32_t)__cvta_generic_to_shared(smem);

    const int tid  = threadIdx.x;
    const int wid  = tid >> 5;
    const int lane = tid & 31;
    const int grp  = lane >> 2;
    const int tig  = lane & 3;
    const int bh   = blockIdx.y;
    const int q0   = blockIdx.x * 128;

    // ldmatrix per-lane offsets (B-operand pattern)
    const int mat = lane >> 3, lr = lane & 7;
    const int b_jo  = mat >> 1;
    const int b_col = (mat & 1) * 8;

    const __nv_bfloat16* Kbh = kh + (size_t)bh * SEQ * HD;
    const __nv_bfloat16* Kbl = kl + (size_t)bh * SEQ * HD;
    const __nv_bfloat16* Vbh = vth + (size_t)bh * HD * SEQ;
    const __nv_bfloat16* Vbl = vtl + (size_t)bh * HD * SEQ;

    auto issue_tile = [&](int kt, int stage) {
        const uint32_t st = sbase + stage * AST;
        #pragma unroll
        for (int i = 0; i < 2; i++) {
            int g = tid + i * 256;
            int r = g >> 3, ch = g & 7;
            uint32_t so = (uint32_t)(r * KPITCH + ch * 8) * 2;
            cp_async16(st + so,         Kbh + (size_t)(kt * 64 + r) * HD + ch * 8);
            cp_async16(st + 9216 + so,  Kbl + (size_t)(kt * 64 + r) * HD + ch * 8);
            cp_async16(st + 18432 + so, Vbh + (size_t)r * SEQ + kt * 64 + ch * 8);
            cp_async16(st + 27648 + so, Vbl + (size_t)r * SEQ + kt * 64 + ch * 8);
        }
        CP_COMMIT();
    };

    issue_tile(0, 0);

    uint32_t qfh[4][4], qfl[4][4];
    {
        const __nv_bfloat16* Qh = qh + ((size_t)bh * SEQ + q0 + wid * 16) * HD;
        const __nv_bfloat16* Ql = ql + ((size_t)bh * SEQ + q0 + wid * 16) * HD;
        #pragma unroll
        for (int cc = 0; cc < 4; cc++) {
            int k0 = cc * 16 + 2 * tig;
            qfh[cc][0] = *(const uint32_t*)(Qh + grp * HD + k0);
            qfh[cc][1] = *(const uint32_t*)(Qh + (grp + 8) * HD + k0);
            qfh[cc][2] = *(const uint32_t*)(Qh + grp * HD + k0 + 8);
            qfh[cc][3] = *(const uint32_t*)(Qh + (grp + 8) * HD + k0 + 8);
            qfl[cc][0] = *(const uint32_t*)(Ql + grp * HD + k0);
            qfl[cc][1] = *(const uint32_t*)(Ql + (grp + 8) * HD + k0);
            qfl[cc][2] = *(const uint32_t*)(Ql + grp * HD + k0 + 8);
            qfl[cc][3] = *(const uint32_t*)(Ql + (grp + 8) * HD + k0 + 8);
        }
    }

    float o[8][4];
    #pragma unroll
    for (int j = 0; j < 8; j++)
        #pragma unroll
        for (int p = 0; p < 4; p++) o[j][p] = 0.f;
    float m0 = -INFINITY, m1 = -INFINITY, l0 = 0.f, l1 = 0.f;

    const int NT = SEQ / 64;
    for (int kt = 0; kt < NT; kt++) {
        if (kt + 1 < NT) {
            issue_tile(kt + 1, (kt + 1) & 1);
            CP_WAIT(1);
        } else {
            CP_WAIT(0);
        }
        __syncthreads();

        const uint32_t st = sbase + (kt & 1) * AST;

        // ---- S = Q K^T (3-pass, ldmatrix) ----
        float s[8][4];
        #pragma unroll
        for (int j = 0; j < 8; j++)
            #pragma unroll
            for (int p = 0; p < 4; p++) s[j][p] = 0.f;
        #pragma unroll
        for (int cc = 0; cc < 4; cc++) {
            #pragma unroll
            for (int p = 0; p < 4; p++) {
                uint32_t kf_h[4], kf_l[4];
                uint32_t kd = st + (uint32_t)(((p * 2 + b_jo) * 8 + lr) * KPITCH
                                              + cc * 16 + b_col) * 2;
                ldsm4(kf_h, kd);
                ldsm4(kf_l, kd + 9216);
                mma16816(s[2 * p],     qfh[cc], &kf_h[0]);
                mma16816(s[2 * p],     qfh[cc], &kf_l[0]);
                mma16816(s[2 * p],     qfl[cc], &kf_h[0]);
                mma16816(s[2 * p + 1], qfh[cc], &kf_h[2]);
                mma16816(s[2 * p + 1], qfh[cc], &kf_l[2]);
                mma16816(s[2 * p + 1], qfl[cc], &kf_h[2]);
            }
        }

        // ---- online softmax ----
        float mx0 = -INFINITY, mx1 = -INFINITY;
        #pragma unroll
        for (int j = 0; j < 8; j++) {
            mx0 = fmaxf(mx0, fmaxf(s[j][0], s[j][1]));
            mx1 = fmaxf(mx1, fmaxf(s[j][2], s[j][3]));
        }
        mx0 = fmaxf(mx0, __shfl_xor_sync(0xffffffffu, mx0, 1));
        mx0 = fmaxf(mx0, __shfl_xor_sync(0xffffffffu, mx0, 2));
        mx1 = fmaxf(mx1, __shfl_xor_sync(0xffffffffu, mx1, 1));
        mx1 = fmaxf(mx1, __shfl_xor_sync(0xffffffffu, mx1, 2));
        float mn0 = fmaxf(m0, mx0), mn1 = fmaxf(m1, mx1);
        float a0 = __expf(m0 - mn0), a1 = __expf(m1 - mn1);
        m0 = mn0; m1 = mn1;

        uint32_t pfh[4][4], pfl[4][4];
        float ps0 = 0.f, ps1 = 0.f;
        #pragma unroll
        for (int j = 0; j < 8; j++) {
            float p0 = __expf(s[j][0] - m0);
            float p1 = __expf(s[j][1] - m0);
            float p2 = __expf(s[j][2] - m1);
            float p3 = __expf(s[j][3] - m1);
            ps0 += p0 + p1;
            ps1 += p2 + p3;
            int cc = j >> 1, half = j & 1;
            __nv_bfloat162 lo2a, lo2b;
            __nv_bfloat162 hi2a = split_pack(p0, p1, &lo2a);
            __nv_bfloat162 hi2b = split_pack(p2, p3, &lo2b);
            pfh[cc][0 + 2 * half] = *(uint32_t*)&hi2a;
            pfh[cc][1 + 2 * half] = *(uint32_t*)&hi2b;
            pfl[cc][0 + 2 * half] = *(uint32_t*)&lo2a;
            pfl[cc][1 + 2 * half] = *(uint32_t*)&lo2b;
        }
        ps0 += __shfl_xor_sync(0xffffffffu, ps0, 1);
        ps0 += __shfl_xor_sync(0xffffffffu, ps0, 2);
        ps1 += __shfl_xor_sync(0xffffffffu, ps1, 1);
        ps1 += __shfl_xor_sync(0xffffffffu, ps1, 2);
        l0 = l0 * a0 + ps0;
        l1 = l1 * a1 + ps1;

        #pragma unroll
        for (int j = 0; j < 8; j++) {
            o[j][0] *= a0; o[j][1] *= a0;
            o[j][2] *= a1; o[j][3] *= a1;
        }

        // ---- O += P V (3-pass, ldmatrix) ----
        #pragma unroll
        for (int cc = 0; cc < 4; cc++) {
            #pragma unroll
            for (int p = 0; p < 4; p++) {
                uint32_t vf_h[4], vf_l[4];
                uint32_t vd = st + 18432 +
                    (uint32_t)(((p * 2 + b_jo) * 8 + lr) * KPITCH + cc * 16 + b_col) * 2;
                ldsm4(vf_h, vd);
                ldsm4(vf_l, vd + 9216);
                mma16816(o[2 * p],     pfh[cc], &vf_h[0]);
                mma16816(o[2 * p],     pfh[cc], &vf_l[0]);
                mma16816(o[2 * p],     pfl[cc], &vf_h[0]);
                mma16816(o[2 * p + 1], pfh[cc], &vf_h[2]);
                mma16816(o[2 * p + 1], pfh[cc], &vf_l[2]);
                mma16816(o[2 * p + 1], pfl[cc], &vf_h[2]);
            }
        }
        __syncthreads();
    }

    // ---- epilogue ----
    const int b = bh >> 4;
    const int h = bh & 15;
    float inv0 = 1.0f / l0, inv1 = 1.0f / l1;
    int s0 = q0 + wid * 16 + grp;
    int s1 = s0 + 8;
    #pragma unroll
    for (int j = 0; j < 8; j++) {
        int col = h * HD + j * 8 + 2 * tig;
        __nv_bfloat162 lo2;
        __nv_bfloat162 hi2 = split_pack(o[j][0] * inv0, o[j][1] * inv0, &lo2);
        size_t off0 = ((size_t)b * SEQ + s0) * HIDDEN + col;
        *(__nv_bfloat162*)(Ohi + off0) = hi2;
        *(__nv_bfloat162*)(Olo + off0) = lo2;
        hi2 = split_pack(o[j][2] * inv1, o[j][3] * inv1, &lo2);
        size_t off1 = ((size_t)b * SEQ + s1) * HIDDEN + col;
        *(__nv_bfloat162*)(Ohi + off1) = hi2;
        *(__nv_bfloat162*)(Olo + off1) = lo2;
    }
}

// ---------------------------------------------------------------------------
extern "C" void kernel_launch(void* const* d_in, const int* in_sizes, int n_in,
                              void* d_out, int out_size)
{
    const float* x     = (const float*)d_in[0];
    const float* W_qkv = (const float*)d_in[1];
    const float* b_qkv = (const float*)d_in[2];
    const float* W_out = (const float*)d_in[3];
    const float* b_out = (const float*)d_in[4];
    float* out = (float*)d_out;

    static __nv_bfloat16 *pah = nullptr, *pal, *pwqh, *pwql, *pwoh, *pwol;
    static __nv_bfloat16 *pqh, *pql, *pkh, *pkl, *pvth, *pvtl;
    if (!pah) {
        cudaGetSymbolAddress((void**)&pah, g_a_hi);
        cudaGetSymbolAddress((void**)&pal, g_a_lo);
        cudaGetSymbolAddress((void**)&pwqh, g_wq_hi);
        cudaGetSymbolAddress((void**)&pwql, g_wq_lo);
        cudaGetSymbolAddress((void**)&pwoh, g_wo_hi);
        cudaGetSymbolAddress((void**)&pwol, g_wo_lo);
        cudaGetSymbolAddress((void**)&pqh, g_qh);
        cudaGetSymbolAddress((void**)&pql, g_ql);
        cudaGetSymbolAddress((void**)&pkh, g_kh);
        cudaGetSymbolAddress((void**)&pkl, g_kl);
        cudaGetSymbolAddress((void**)&pvth, g_vth);
        cudaGetSymbolAddress((void**)&pvtl, g_vtl);
        cudaFuncSetAttribute(hmma_gemm, cudaFuncAttributeMaxDynamicSharedMemorySize, GEMM_SMEM);
        cudaFuncSetAttribute(attn_hmma, cudaFuncAttributeMaxDynamicSharedMemorySize, ATTN_SMEM);
    }

    const int n4 = MTOT * HIDDEN / 4;

    split_kernel<<<n4 / 256, 256>>>(x, pah, pal, n4);
    {
        dim3 g(3 * HIDDEN / 32, HIDDEN / 32);
        tsplit_kernel<<<g, dim3(32, 8)>>>(W_qkv, pwqh, pwql, HIDDEN, 3 * HIDDEN);
    }
    {
        dim3 g(HIDDEN / 32, HIDDEN / 32);
        tsplit_kernel<<<g, dim3(32, 8)>>>(W_out, pwoh, pwol, HIDDEN, HIDDEN);
    }

    {
        dim3 g(3 * HIDDEN / 128, MTOT / 128);
        hmma_gemm<<<g, 256, GEMM_SMEM>>>(pah, pal, pwqh, pwql, b_qkv, nullptr,
                                         pqh, pql, pkh, pkl, pvth, pvtl,
                                         MTOT, 3 * HIDDEN, HIDDEN, 1);
    }

    {
        dim3 g(SEQ / 128, BATCH * HEADS);
        attn_hmma<<<g, 256, ATTN_SMEM>>>(pqh, pql, pkh, pkl, pvth, pvtl, pah, pal);
    }

    {
        dim3 g(HIDDEN / 128, MTOT / 128);
        hmma_gemm<<<g, 256, GEMM_SMEM>>>(pah, pal, pwoh, pwol, b_out, out,
                                         nullptr, nullptr, nullptr, nullptr, nullptr, nullptr,
                                         MTOT, HIDDEN, HIDDEN, 0);
    }
}